// round 6
// baseline (speedup 1.0000x reference)
#include <cuda_runtime.h>
#include <cuda_fp16.h>
#include <cstdint>

#define DD 1024
#define HH 4096
#define NB 8
#define LL 768
#define MT 6144   // NB*LL
#define NE 4

#define KCH 64               // K halfs per chunk (128B rows)
#define SS 2                 // pipeline stages
#define TILEA_BYTES 16384    // 128 rows x 128B
#define STG_BYTES 32768      // A tile + B tile
#define GEMM_SMEM (SS * STG_BYTES)   // 64 KB -> 3 CTAs/SM

// ---------------- scratch (device globals; no allocation) ----------------
__device__ __align__(256) __half g_Xh[(size_t)MT * DD];
__device__ __align__(256) __half g_W1e[(size_t)NE * HH * DD];  // W1^T per expert: [H][D]
__device__ __align__(256) __half g_W2e[(size_t)NE * DD * HH];  // W2^T per expert: [D][H]
__device__ __align__(256) __half g_W1s[(size_t)HH * DD];       // sw1^T
__device__ __align__(256) __half g_W2s[(size_t)DD * HH];       // sw2^T
__device__ __align__(256) __half g_H[(size_t)5 * MT * HH];     // [shared, e0..e3] hidden
__device__ float  g_partial[NB * 6 * DD];
__device__ float  g_wbe[NB * NE];

// ---------------- helpers ----------------
__device__ __forceinline__ uint32_t smem_u32(const void* p) {
    uint32_t a;
    asm("{ .reg .u64 t; cvta.to.shared.u64 t, %1; cvt.u32.u64 %0, t; }" : "=r"(a) : "l"(p));
    return a;
}
__device__ __forceinline__ void cp_async16(void* smem, const void* gmem) {
    unsigned s = (unsigned)__cvta_generic_to_shared(smem);
    asm volatile("cp.async.cg.shared.global [%0], [%1], 16;\n" :: "r"(s), "l"(gmem) : "memory");
}
__device__ __forceinline__ void cp_commit() { asm volatile("cp.async.commit_group;\n" ::: "memory"); }

__device__ __forceinline__ void ldm4(uint32_t* r, uint32_t addr) {
    asm volatile("ldmatrix.sync.aligned.m8n8.x4.shared.b16 {%0,%1,%2,%3}, [%4];"
        : "=r"(r[0]), "=r"(r[1]), "=r"(r[2]), "=r"(r[3]) : "r"(addr));
}
__device__ __forceinline__ void mma16816(float* c, const uint32_t* a, const uint32_t* b) {
    asm volatile(
        "mma.sync.aligned.m16n8k16.row.col.f32.f16.f16.f32 "
        "{%0,%1,%2,%3}, {%4,%5,%6,%7}, {%8,%9}, {%0,%1,%2,%3};"
        : "+f"(c[0]), "+f"(c[1]), "+f"(c[2]), "+f"(c[3])
        : "r"(a[0]), "r"(a[1]), "r"(a[2]), "r"(a[3]), "r"(b[0]), "r"(b[1]));
}

__device__ __forceinline__ float gelu_t(float v) {
    float c = v + 0.044715f * v * v * v;
    return 0.5f * v * (1.f + tanhf(0.7978845608028654f * c));
}

// per-M-tile weight: batch gating weight x third-mask; exact 0 => skip tile
__device__ __forceinline__ float tile_weight(int expert, int bm) {
    if (expert < 0) return 1.f;
    int b = bm / 6;             // 6 tiles of 128 tokens per batch
    int third = (bm % 6) >> 1;  // 0 head, 1 wrist, 2 proprio
    if (expert == 1 && third == 1) return 0.f;
    if (expert == 2 && third == 0) return 0.f;
    return g_wbe[b * NE + expert];
}

// ---------------- gating stage A ----------------
__global__ void k_stageA(const float* __restrict__ x) {
    int b = blockIdx.x, c = blockIdx.y, t = threadIdx.x;
    const float* base = x + ((size_t)(b * LL + c * 128)) * DD;
    for (int d = t; d < DD; d += 256) {
        float s = 0.f;
        #pragma unroll 4
        for (int l = 0; l < 128; ++l) s += base[(size_t)l * DD + d];
        g_partial[(b * 6 + c) * DD + d] = s;
    }
}

// ---------------- gating stage B ----------------
__global__ void k_gate(const float* __restrict__ gate_w, const float* __restrict__ gate_b,
                       const float* __restrict__ time_cond, const float* __restrict__ time_w,
                       const float* __restrict__ time_b)
{
    int b = blockIdx.x, t = threadIdx.x;
    __shared__ float red[12][256];
    float acc[12];
    #pragma unroll
    for (int k = 0; k < 12; k++) acc[k] = 0.f;
    for (int d = t; d < DD; d += 256) {
        float h = g_partial[(b*6+0)*DD+d] + g_partial[(b*6+1)*DD+d];
        float w = g_partial[(b*6+2)*DD+d] + g_partial[(b*6+3)*DD+d];
        float p = g_partial[(b*6+4)*DD+d] + g_partial[(b*6+5)*DD+d];
        float full = (h + w + p) * (1.f / 768.f);
        float hp   = (h + p) * (1.f / 512.f);
        float wp   = (w + p) * (1.f / 512.f);
        #pragma unroll
        for (int e = 0; e < 4; e++)
            acc[e] += full * gate_w[d*4+e] + hp * gate_w[(DD+d)*4+e] + wp * gate_w[(2*DD+d)*4+e];
        float tc = time_cond[b * DD + d];
        float s  = tc / (1.f + expf(-tc));   // silu
        #pragma unroll
        for (int j = 0; j < 8; j++) acc[4 + j] += s * time_w[d*8 + j];
    }
    #pragma unroll
    for (int k = 0; k < 12; k++) red[k][t] = acc[k];
    __syncthreads();
    for (int s = 128; s > 0; s >>= 1) {
        if (t < s) {
            #pragma unroll
            for (int k = 0; k < 12; k++) red[k][t] += red[k][t + s];
        }
        __syncthreads();
    }
    if (t == 0) {
        float logit[4], prob[4];
        #pragma unroll
        for (int e = 0; e < 4; e++) {
            float sc = red[4 + e][0] + time_b[e];
            float sh = red[8 + e][0] + time_b[4 + e];
            logit[e] = (red[e][0] + gate_b[e]) * (1.f + sc) + sh;
        }
        float mx = fmaxf(fmaxf(logit[0], logit[1]), fmaxf(logit[2], logit[3]));
        float sum = 0.f;
        for (int e = 0; e < 4; e++) { prob[e] = expf(logit[e] - mx); sum += prob[e]; }
        for (int e = 0; e < 4; e++) prob[e] /= sum;
        int i1 = 0;
        for (int e = 1; e < 4; e++) if (prob[e] > prob[i1]) i1 = e;
        int i2 = -1;
        for (int e = 0; e < 4; e++) if (e != i1 && (i2 < 0 || prob[e] > prob[i2])) i2 = e;
        float denom = prob[i1] + prob[i2] + 1e-8f;
        #pragma unroll
        for (int e = 0; e < 4; e++) g_wbe[b * NE + e] = 0.f;
        g_wbe[b * NE + i1] = prob[i1] / denom;
        g_wbe[b * NE + i2] = prob[i2] / denom;
    }
}

// ---------------- fp32 -> fp16 straight convert (x -> g_Xh) ----------------
__global__ void k_f2h(const float* __restrict__ src, int n4) {
    int stride = gridDim.x * blockDim.x;
    for (int i = blockIdx.x * blockDim.x + threadIdx.x; i < n4; i += stride) {
        float4 v = reinterpret_cast<const float4*>(src)[i];
        __half2* d2 = reinterpret_cast<__half2*>(g_Xh) + (size_t)i * 2;
        d2[0] = __floats2half2_rn(v.x, v.y);
        d2[1] = __floats2half2_rn(v.z, v.w);
    }
}

// ---------------- fp32 [R,C] -> fp16 transposed [C,R]; z<NE experts, z==NE shared ----------------
// W: 0 -> (ew*, sw1 -> g_W1e/g_W1s), 1 -> (ew2, sw2 -> g_W2e/g_W2s)
template<int W>
__global__ void k_f2ht(const float* __restrict__ src_e, const float* __restrict__ src_s,
                       int R, int C) {
    int e = blockIdx.z;
    const float* src;
    __half* dst;
    if (e < NE) {
        src = src_e + (size_t)e * R * C;
        dst = (W == 0 ? g_W1e : g_W2e) + (size_t)e * R * C;
    } else {
        src = src_s;
        dst = (W == 0) ? g_W1s : g_W2s;
    }
    __shared__ float t[32][33];
    int c0 = blockIdx.x * 32, r0 = blockIdx.y * 32;
    int tx = threadIdx.x, ty = threadIdx.y;
    #pragma unroll
    for (int j = 0; j < 32; j += 8)
        t[ty + j][tx] = src[(size_t)(r0 + ty + j) * C + c0 + tx];
    __syncthreads();
    #pragma unroll
    for (int j = 0; j < 32; j += 8)
        dst[(size_t)(c0 + ty + j) * R + r0 + tx] = __float2half(t[tx][ty + j]);
}

// ---------------- fused mma.sync GEMM: CTA 128x128, 4 warps, warp tile 64x64, 3 CTA/SM ----------------
// MODE 0 (GEMM1): z selects buffer (0 shared, 1..4 experts). H[z] = w * gelu(X@W1 + b1)
// MODE 1 (GEMM2): out = sum over active segs: H[s] @ W2[s] + combined bias (single write)
template<int MODE>
__global__ void __launch_bounds__(128, 3) k_mma(
    const float* __restrict__ b_sh, const float* __restrict__ b_ex,
    float* __restrict__ fout)
{
    int bm = blockIdx.x, bn = blockIdx.y, z = blockIdx.z;
    __shared__ const __half* sA[5];
    __shared__ const __half* sB[5];
    __shared__ const float* sBias[5];
    __shared__ float sW[5];
    __shared__ int sNs;

    int Ks, nch;
    float scale = 1.f;
    __half* hout = nullptr;

    if (MODE == 0) {
        float w = tile_weight(z - 1, bm);
        if (w == 0.f) return;
        scale = w;
        if (threadIdx.x == 0) {
            sA[0] = g_Xh;
            sB[0] = (z == 0) ? g_W1s : (g_W1e + (size_t)(z - 1) * HH * DD);
            sBias[0] = (z == 0) ? b_sh : (b_ex + (size_t)(z - 1) * HH);
            sNs = 1;
        }
        Ks = DD;
        hout = g_H + (size_t)z * MT * HH;
    } else {
        if (threadIdx.x == 0) {
            int ns = 0;
            sA[ns] = g_H; sB[ns] = g_W2s; sBias[ns] = b_sh; sW[ns] = 1.f; ns++;
            for (int e = 0; e < NE; e++) {
                float w = tile_weight(e, bm);
                if (w > 0.f) {
                    sA[ns] = g_H + (size_t)(e + 1) * MT * HH;
                    sB[ns] = g_W2e + (size_t)e * DD * HH;
                    sBias[ns] = b_ex + (size_t)e * DD;
                    sW[ns] = w;
                    ns++;
                }
            }
            sNs = ns;
        }
        Ks = HH;
    }
    __syncthreads();
    int ns = sNs;
    nch = (MODE == 0) ? (DD / KCH) : ns * (HH / KCH);

    extern __shared__ __align__(128) char smem[];
    uint32_t sbase = smem_u32(smem);
    int tid = threadIdx.x, lane = tid & 31, wid = tid >> 5;
    int wm = wid & 1, wn = wid >> 1;          // 2x2 warps, 64x64 each
    int m0 = bm * 128, n0 = bn * 128;

    auto issue = [&](int flat, int slot) {
        int seg = flat >> 6;
        int koff = (flat & 63) * KCH;
        const __half* Ab = sA[seg] + koff;
        const __half* Bb = sB[seg] + koff;
        char* st = smem + slot * STG_BYTES;
        #pragma unroll
        for (int i = 0; i < 8; i++) {
            int idx = tid + i * 128;
            int r = idx >> 3, c8 = idx & 7;
            uint32_t off = (uint32_t)(r * 128 + c8 * 16);
            off ^= (off >> 3) & 0x70;
            cp_async16(st + off, Ab + (size_t)(m0 + r) * Ks + c8 * 8);
        }
        #pragma unroll
        for (int i = 0; i < 8; i++) {
            int idx = tid + i * 128;
            int r = idx >> 3, c8 = idx & 7;
            uint32_t off = (uint32_t)(r * 128 + c8 * 16);
            off ^= (off >> 3) & 0x70;
            cp_async16(st + TILEA_BYTES + off, Bb + (size_t)(n0 + r) * Ks + c8 * 8);
        }
        cp_commit();
    };

    float c[4][8][4];
    #pragma unroll
    for (int i = 0; i < 4; i++)
        #pragma unroll
        for (int j = 0; j < 8; j++)
            #pragma unroll
            for (int q = 0; q < 4; q++) c[i][j][q] = 0.f;

    issue(0, 0);

    for (int it = 0; it < nch; ++it) {
        // prefetch next chunk into the other buffer (safe: all warps finished
        // reading it at the end-of-iteration barrier of it-1)
        if (it + 1 < nch) {
            issue(it + 1, (it + 1) & 1);
            asm volatile("cp.async.wait_group 1;" ::: "memory");
        } else {
            asm volatile("cp.async.wait_group 0;" ::: "memory");
        }
        __syncthreads();

        uint32_t sAb = sbase + (it & 1) * STG_BYTES;
        uint32_t sBb = sAb + TILEA_BYTES;
        #pragma unroll
        for (int kk = 0; kk < 4; kk++) {
            uint32_t a[4][4];
            #pragma unroll
            for (int i = 0; i < 4; i++) {
                int row = wm * 64 + i * 16 + (lane & 15);
                uint32_t off = (uint32_t)(row * 128 + kk * 32 + ((lane >> 4) & 1) * 16);
                off ^= (off >> 3) & 0x70;
                ldm4(a[i], sAb + off);
            }
            #pragma unroll
            for (int jp = 0; jp < 4; jp++) {
                int n = wn * 64 + jp * 16 + ((lane >> 4) & 1) * 8 + (lane & 7);
                uint32_t off = (uint32_t)(n * 128 + kk * 32 + ((lane >> 3) & 1) * 16);
                off ^= (off >> 3) & 0x70;
                uint32_t b4[4];
                ldm4(b4, sBb + off);
                #pragma unroll
                for (int i = 0; i < 4; i++) {
                    mma16816(c[i][2 * jp],     a[i], b4);
                    mma16816(c[i][2 * jp + 1], a[i], b4 + 2);
                }
            }
        }
        __syncthreads();   // all warps done reading this buffer before it is refilled
    }

    // ---- epilogue (register-direct) ----
    int gid = lane >> 2, tig = lane & 3;
    if (MODE == 0) {
        #pragma unroll
        for (int i = 0; i < 4; i++) {
            int r0i = m0 + wm * 64 + i * 16 + gid;
            #pragma unroll
            for (int j = 0; j < 8; j++) {
                int col = n0 + wn * 64 + j * 8 + tig * 2;
                float b0 = __ldg(sBias[0] + col);
                float b1 = __ldg(sBias[0] + col + 1);
                __half2 h0 = __floats2half2_rn(scale * gelu_t(c[i][j][0] + b0),
                                               scale * gelu_t(c[i][j][1] + b1));
                __half2 h1 = __floats2half2_rn(scale * gelu_t(c[i][j][2] + b0),
                                               scale * gelu_t(c[i][j][3] + b1));
                *reinterpret_cast<__half2*>(hout + (size_t)r0i * HH + col) = h0;
                *reinterpret_cast<__half2*>(hout + (size_t)(r0i + 8) * HH + col) = h1;
            }
        }
    } else {
        #pragma unroll
        for (int i = 0; i < 4; i++) {
            int r0i = m0 + wm * 64 + i * 16 + gid;
            #pragma unroll
            for (int j = 0; j < 8; j++) {
                int col = n0 + wn * 64 + j * 8 + tig * 2;
                float b0 = __ldg(sBias[0] + col);
                float b1 = __ldg(sBias[0] + col + 1);
                for (int s = 1; s < ns; s++) {
                    b0 += sW[s] * __ldg(sBias[s] + col);
                    b1 += sW[s] * __ldg(sBias[s] + col + 1);
                }
                float2 v0 = make_float2(c[i][j][0] + b0, c[i][j][1] + b1);
                float2 v1 = make_float2(c[i][j][2] + b0, c[i][j][3] + b1);
                *reinterpret_cast<float2*>(fout + (size_t)r0i * DD + col) = v0;
                *reinterpret_cast<float2*>(fout + (size_t)(r0i + 8) * DD + col) = v1;
            }
        }
    }
}

// ---------------- launch ----------------
extern "C" void kernel_launch(void* const* d_in, const int* in_sizes, int n_in,
                              void* d_out, int out_size)
{
    (void)in_sizes; (void)n_in; (void)out_size;
    const float* x         = (const float*)d_in[0];
    const float* time_cond = (const float*)d_in[1];
    const float* gate_w    = (const float*)d_in[2];
    const float* gate_b    = (const float*)d_in[3];
    const float* time_w    = (const float*)d_in[4];
    const float* time_b    = (const float*)d_in[5];
    const float* ew1       = (const float*)d_in[6];
    const float* eb1       = (const float*)d_in[7];
    const float* ew2       = (const float*)d_in[8];
    const float* eb2       = (const float*)d_in[9];
    const float* sw1       = (const float*)d_in[10];
    const float* sb1       = (const float*)d_in[11];
    const float* sw2       = (const float*)d_in[12];
    const float* sb2       = (const float*)d_in[13];
    float* out = (float*)d_out;

    cudaFuncSetAttribute(k_mma<0>, cudaFuncAttributeMaxDynamicSharedMemorySize, GEMM_SMEM);
    cudaFuncSetAttribute(k_mma<1>, cudaFuncAttributeMaxDynamicSharedMemorySize, GEMM_SMEM);

    // gating
    k_stageA<<<dim3(8, 6), 256>>>(x);
    k_gate<<<8, 256>>>(gate_w, gate_b, time_cond, time_w, time_b);

    // conversions: x straight; weights transposed to [N][K] fp16 (z=4 is shared expert)
    k_f2h<<<2048, 256>>>(x, MT * DD / 4);
    k_f2ht<0><<<dim3(HH / 32, DD / 32, NE + 1), dim3(32, 8)>>>(ew1, sw1, DD, HH); // [D,H]->[H,D]
    k_f2ht<1><<<dim3(DD / 32, HH / 32, NE + 1), dim3(32, 8)>>>(ew2, sw2, HH, DD); // [H,D]->[D,H]

    // GEMM1: shared + 4 experts in one launch (z dim); inactive tiles exit
    k_mma<0><<<dim3(MT / 128, HH / 128, 5), 128, GEMM_SMEM>>>(sb1, eb1, nullptr);
    // GEMM2: fused accumulation over active segments, single write of out
    k_mma<1><<<dim3(MT / 128, DD / 128, 1), 128, GEMM_SMEM>>>(sb2, eb2, out);
}

// round 7
// speedup vs baseline: 1.1442x; 1.1442x over previous
#include <cuda_runtime.h>
#include <cuda_fp16.h>
#include <cstdint>

#define DD 1024
#define HH 4096
#define NB 8
#define LL 768
#define MT 6144   // NB*LL
#define NE 4

#define KCH 64               // K halfs per chunk (128B rows)
#define SS 3                 // pipeline stages
#define TILE_BYTES 16384     // 128 rows x 128B
#define STG_BYTES 32768      // A tile + B tile
#define GEMM_SMEM (SS * STG_BYTES)   // 96 KB -> 2 CTAs/SM

// ---------------- scratch (device globals; no allocation) ----------------
__device__ __align__(256) __half g_Xh[(size_t)MT * DD];
__device__ __align__(256) __half g_W1e[(size_t)NE * HH * DD];  // W1^T per expert: [H][D]
__device__ __align__(256) __half g_W2e[(size_t)NE * DD * HH];  // W2^T per expert: [D][H]
__device__ __align__(256) __half g_W1s[(size_t)HH * DD];       // sw1^T
__device__ __align__(256) __half g_W2s[(size_t)DD * HH];       // sw2^T
__device__ __align__(256) __half g_H[(size_t)5 * MT * HH];     // [shared, e0..e3] hidden
__device__ float  g_partial[NB * 6 * DD];
__device__ float  g_wbe[NB * NE];

// ---------------- helpers ----------------
__device__ __forceinline__ uint32_t smem_u32(const void* p) {
    uint32_t a;
    asm("{ .reg .u64 t; cvta.to.shared.u64 t, %1; cvt.u32.u64 %0, t; }" : "=r"(a) : "l"(p));
    return a;
}
__device__ __forceinline__ void cp_async16(void* smem, const void* gmem) {
    unsigned s = (unsigned)__cvta_generic_to_shared(smem);
    asm volatile("cp.async.cg.shared.global [%0], [%1], 16;\n" :: "r"(s), "l"(gmem) : "memory");
}
__device__ __forceinline__ void cp_commit() { asm volatile("cp.async.commit_group;\n" ::: "memory"); }

__device__ __forceinline__ void ldm4(uint32_t* r, uint32_t addr) {
    asm volatile("ldmatrix.sync.aligned.m8n8.x4.shared.b16 {%0,%1,%2,%3}, [%4];"
        : "=r"(r[0]), "=r"(r[1]), "=r"(r[2]), "=r"(r[3]) : "r"(addr));
}
__device__ __forceinline__ void mma16816(float* c, const uint32_t* a, const uint32_t* b) {
    asm volatile(
        "mma.sync.aligned.m16n8k16.row.col.f32.f16.f16.f32 "
        "{%0,%1,%2,%3}, {%4,%5,%6,%7}, {%8,%9}, {%0,%1,%2,%3};"
        : "+f"(c[0]), "+f"(c[1]), "+f"(c[2]), "+f"(c[3])
        : "r"(a[0]), "r"(a[1]), "r"(a[2]), "r"(a[3]), "r"(b[0]), "r"(b[1]));
}

__device__ __forceinline__ float gelu_t(float v) {
    float c = v + 0.044715f * v * v * v;
    return 0.5f * v * (1.f + tanhf(0.7978845608028654f * c));
}

// per-M-tile weight: batch gating weight x third-mask; exact 0 => skip tile
__device__ __forceinline__ float tile_weight(int expert, int bm) {
    if (expert < 0) return 1.f;
    int b = bm / 6;             // 6 tiles of 128 tokens per batch
    int third = (bm % 6) >> 1;  // 0 head, 1 wrist, 2 proprio
    if (expert == 1 && third == 1) return 0.f;
    if (expert == 2 && third == 0) return 0.f;
    return g_wbe[b * NE + expert];
}

// ---------------- merged conversion kernel ----------------
// z == 0       : x fp32 -> fp16 straight into g_Xh (flat, grid-stride inside slice)
// z in 1..NE   : ew1 expert z-1  [D,H] -> transposed [H,D] into g_W1e
// z == NE+1    : sw1 [D,H] -> g_W1s
// z in NE+2..2NE+1 : ew2 expert z-NE-2 [H,D] -> [D,H] into g_W2e
// z == 2NE+2   : sw2 [H,D] -> g_W2s
__global__ void k_conv(const float* __restrict__ x,
                       const float* __restrict__ ew1, const float* __restrict__ sw1,
                       const float* __restrict__ ew2, const float* __restrict__ sw2)
{
    int z = blockIdx.z;
    if (z == 0) {
        // x convert: MT*DD/4 float4 elements over grid.x*blockDim
        int n4 = MT * DD / 4;
        int stride = gridDim.x * blockDim.x * blockDim.y;
        int tid = (threadIdx.y * blockDim.x + threadIdx.x) + blockIdx.x * (blockDim.x * blockDim.y);
        for (int i = tid; i < n4; i += stride) {
            float4 v = reinterpret_cast<const float4*>(x)[i];
            __half2* d2 = reinterpret_cast<__half2*>(g_Xh) + (size_t)i * 2;
            d2[0] = __floats2half2_rn(v.x, v.y);
            d2[1] = __floats2half2_rn(v.z, v.w);
        }
        return;
    }
    // transpose slices
    const float* src;
    __half* dst;
    int R, C;
    if (z <= NE + 1) {                 // W1 family: [D,H] -> [H,D]
        R = DD; C = HH;
        if (z <= NE) { src = ew1 + (size_t)(z - 1) * R * C; dst = g_W1e + (size_t)(z - 1) * R * C; }
        else         { src = sw1; dst = g_W1s; }
    } else {                           // W2 family: [H,D] -> [D,H]
        R = HH; C = DD;
        int e = z - NE - 2;
        if (e < NE) { src = ew2 + (size_t)e * R * C; dst = g_W2e + (size_t)e * R * C; }
        else        { src = sw2; dst = g_W2s; }
    }
    // flat block index -> (cb, rb) over (C/32) x (R/32)
    int nCB = C / 32;
    int bx = blockIdx.x % nCB;
    int by = blockIdx.x / nCB;
    if (by >= R / 32) return;
    __shared__ float t[32][33];
    int c0 = bx * 32, r0 = by * 32;
    int tx = threadIdx.x, ty = threadIdx.y;
    #pragma unroll
    for (int j = 0; j < 32; j += 8)
        t[ty + j][tx] = src[(size_t)(r0 + ty + j) * C + c0 + tx];
    __syncthreads();
    #pragma unroll
    for (int j = 0; j < 32; j += 8)
        dst[(size_t)(c0 + ty + j) * R + r0 + tx] = __float2half(t[tx][ty + j]);
}

// ---------------- gating stage A ----------------
__global__ void k_stageA(const float* __restrict__ x) {
    int b = blockIdx.x, c = blockIdx.y, t = threadIdx.x;
    const float* base = x + ((size_t)(b * LL + c * 128)) * DD;
    for (int d = t; d < DD; d += 256) {
        float s = 0.f;
        #pragma unroll 4
        for (int l = 0; l < 128; ++l) s += base[(size_t)l * DD + d];
        g_partial[(b * 6 + c) * DD + d] = s;
    }
}

// ---------------- gating stage B ----------------
__global__ void k_gate(const float* __restrict__ gate_w, const float* __restrict__ gate_b,
                       const float* __restrict__ time_cond, const float* __restrict__ time_w,
                       const float* __restrict__ time_b)
{
    int b = blockIdx.x, t = threadIdx.x;
    __shared__ float red[12][256];
    float acc[12];
    #pragma unroll
    for (int k = 0; k < 12; k++) acc[k] = 0.f;
    for (int d = t; d < DD; d += 256) {
        float h = g_partial[(b*6+0)*DD+d] + g_partial[(b*6+1)*DD+d];
        float w = g_partial[(b*6+2)*DD+d] + g_partial[(b*6+3)*DD+d];
        float p = g_partial[(b*6+4)*DD+d] + g_partial[(b*6+5)*DD+d];
        float full = (h + w + p) * (1.f / 768.f);
        float hp   = (h + p) * (1.f / 512.f);
        float wp   = (w + p) * (1.f / 512.f);
        #pragma unroll
        for (int e = 0; e < 4; e++)
            acc[e] += full * gate_w[d*4+e] + hp * gate_w[(DD+d)*4+e] + wp * gate_w[(2*DD+d)*4+e];
        float tc = time_cond[b * DD + d];
        float s  = tc / (1.f + expf(-tc));   // silu
        #pragma unroll
        for (int j = 0; j < 8; j++) acc[4 + j] += s * time_w[d*8 + j];
    }
    #pragma unroll
    for (int k = 0; k < 12; k++) red[k][t] = acc[k];
    __syncthreads();
    for (int s = 128; s > 0; s >>= 1) {
        if (t < s) {
            #pragma unroll
            for (int k = 0; k < 12; k++) red[k][t] += red[k][t + s];
        }
        __syncthreads();
    }
    if (t == 0) {
        float logit[4], prob[4];
        #pragma unroll
        for (int e = 0; e < 4; e++) {
            float sc = red[4 + e][0] + time_b[e];
            float sh = red[8 + e][0] + time_b[4 + e];
            logit[e] = (red[e][0] + gate_b[e]) * (1.f + sc) + sh;
        }
        float mx = fmaxf(fmaxf(logit[0], logit[1]), fmaxf(logit[2], logit[3]));
        float sum = 0.f;
        for (int e = 0; e < 4; e++) { prob[e] = expf(logit[e] - mx); sum += prob[e]; }
        for (int e = 0; e < 4; e++) prob[e] /= sum;
        int i1 = 0;
        for (int e = 1; e < 4; e++) if (prob[e] > prob[i1]) i1 = e;
        int i2 = -1;
        for (int e = 0; e < 4; e++) if (e != i1 && (i2 < 0 || prob[e] > prob[i2])) i2 = e;
        float denom = prob[i1] + prob[i2] + 1e-8f;
        #pragma unroll
        for (int e = 0; e < 4; e++) g_wbe[b * NE + e] = 0.f;
        g_wbe[b * NE + i1] = prob[i1] / denom;
        g_wbe[b * NE + i2] = prob[i2] / denom;
    }
}

// ---------------- fused mma.sync GEMM (R3 config: 8 warps, warp tile 32x64) ----------------
// MODE 0 (GEMM1): z selects buffer (0 shared, 1..4 experts). H[z] = w * gelu(X@W1 + b1)
// MODE 1 (GEMM2): out = sum over active segs: H[s] @ W2[s] + combined bias (single write)
template<int MODE>
__global__ void __launch_bounds__(256, 2) k_mma(
    const float* __restrict__ b_sh, const float* __restrict__ b_ex,
    float* __restrict__ fout)
{
    int bm = blockIdx.x, bn = blockIdx.y, z = blockIdx.z;
    __shared__ const __half* sA[5];
    __shared__ const __half* sB[5];
    __shared__ const float* sBias[5];
    __shared__ float sW[5];
    __shared__ int sNs;

    int Ks, nch;
    float scale = 1.f;
    __half* hout = nullptr;

    if (MODE == 0) {
        float w = tile_weight(z - 1, bm);
        if (w == 0.f) return;
        scale = w;
        if (threadIdx.x == 0) {
            sA[0] = g_Xh;
            sB[0] = (z == 0) ? g_W1s : (g_W1e + (size_t)(z - 1) * HH * DD);
            sBias[0] = (z == 0) ? b_sh : (b_ex + (size_t)(z - 1) * HH);
            sNs = 1;
        }
        Ks = DD;
        hout = g_H + (size_t)z * MT * HH;
    } else {
        if (threadIdx.x == 0) {
            int ns = 0;
            sA[ns] = g_H; sB[ns] = g_W2s; sBias[ns] = b_sh; sW[ns] = 1.f; ns++;
            for (int e = 0; e < NE; e++) {
                float w = tile_weight(e, bm);
                if (w > 0.f) {
                    sA[ns] = g_H + (size_t)(e + 1) * MT * HH;
                    sB[ns] = g_W2e + (size_t)e * DD * HH;
                    sBias[ns] = b_ex + (size_t)e * DD;
                    sW[ns] = w;
                    ns++;
                }
            }
            sNs = ns;
        }
        Ks = HH;
    }
    __syncthreads();
    int ns = sNs;
    nch = (MODE == 0) ? (DD / KCH) : ns * (HH / KCH);

    extern __shared__ __align__(128) char smem[];
    uint32_t sbase = smem_u32(smem);
    int tid = threadIdx.x, lane = tid & 31, wid = tid >> 5;
    int wm = wid & 3, wn = wid >> 2;          // 4x2 warps, warp tile 32x64
    int m0 = bm * 128, n0 = bn * 128;

    auto issue = [&](int flat, int slot) {
        int seg = flat >> 6;
        int koff = (flat & 63) * KCH;
        const __half* Ab = sA[seg] + koff;
        const __half* Bb = sB[seg] + koff;
        char* st = smem + slot * STG_BYTES;
        #pragma unroll
        for (int i = 0; i < 4; i++) {
            int idx = tid + i * 256;
            int r = idx >> 3, c8 = idx & 7;
            uint32_t off = (uint32_t)(r * 128 + c8 * 16);
            off ^= (off >> 3) & 0x70;
            cp_async16(st + off, Ab + (size_t)(m0 + r) * Ks + c8 * 8);
        }
        #pragma unroll
        for (int i = 0; i < 4; i++) {
            int idx = tid + i * 256;
            int r = idx >> 3, c8 = idx & 7;
            uint32_t off = (uint32_t)(r * 128 + c8 * 16);
            off ^= (off >> 3) & 0x70;
            cp_async16(st + TILE_BYTES + off, Bb + (size_t)(n0 + r) * Ks + c8 * 8);
        }
        cp_commit();
    };

    float c[2][8][4];
    #pragma unroll
    for (int i = 0; i < 2; i++)
        #pragma unroll
        for (int j = 0; j < 8; j++)
            #pragma unroll
            for (int q = 0; q < 4; q++) c[i][j][q] = 0.f;

    issue(0, 0);
    issue(1, 1);

    for (int it = 0; it < nch; ++it) {
        if (it + 1 < nch) asm volatile("cp.async.wait_group 1;" ::: "memory");
        else              asm volatile("cp.async.wait_group 0;" ::: "memory");
        __syncthreads();
        if (it + 2 < nch) issue(it + 2, (it + 2) % SS);

        uint32_t sAb = sbase + (it % SS) * STG_BYTES;
        uint32_t sBb = sAb + TILE_BYTES;
        #pragma unroll
        for (int kk = 0; kk < 4; kk++) {
            uint32_t a[2][4];
            #pragma unroll
            for (int i = 0; i < 2; i++) {
                int row = wm * 32 + i * 16 + (lane & 15);
                uint32_t off = (uint32_t)(row * 128 + kk * 32 + ((lane >> 4) & 1) * 16);
                off ^= (off >> 3) & 0x70;
                ldm4(a[i], sAb + off);
            }
            uint32_t b[8][2];
            #pragma unroll
            for (int jp = 0; jp < 4; jp++) {
                int n = wn * 64 + jp * 16 + ((lane >> 4) & 1) * 8 + (lane & 7);
                uint32_t off = (uint32_t)(n * 128 + kk * 32 + ((lane >> 3) & 1) * 16);
                off ^= (off >> 3) & 0x70;
                uint32_t r4[4];
                ldm4(r4, sBb + off);
                b[2 * jp][0] = r4[0]; b[2 * jp][1] = r4[1];
                b[2 * jp + 1][0] = r4[2]; b[2 * jp + 1][1] = r4[3];
            }
            #pragma unroll
            for (int i = 0; i < 2; i++)
                #pragma unroll
                for (int j = 0; j < 8; j++)
                    mma16816(c[i][j], a[i], b[j]);
        }
    }

    // ---- epilogue (register-direct) ----
    int gid = lane >> 2, tig = lane & 3;
    if (MODE == 0) {
        #pragma unroll
        for (int i = 0; i < 2; i++) {
            int r0i = m0 + wm * 32 + i * 16 + gid;
            #pragma unroll
            for (int j = 0; j < 8; j++) {
                int col = n0 + wn * 64 + j * 8 + tig * 2;
                float b0 = __ldg(sBias[0] + col);
                float b1 = __ldg(sBias[0] + col + 1);
                __half2 h0 = __floats2half2_rn(scale * gelu_t(c[i][j][0] + b0),
                                               scale * gelu_t(c[i][j][1] + b1));
                __half2 h1 = __floats2half2_rn(scale * gelu_t(c[i][j][2] + b0),
                                               scale * gelu_t(c[i][j][3] + b1));
                *reinterpret_cast<__half2*>(hout + (size_t)r0i * HH + col) = h0;
                *reinterpret_cast<__half2*>(hout + (size_t)(r0i + 8) * HH + col) = h1;
            }
        }
    } else {
        #pragma unroll
        for (int i = 0; i < 2; i++) {
            int r0i = m0 + wm * 32 + i * 16 + gid;
            #pragma unroll
            for (int j = 0; j < 8; j++) {
                int col = n0 + wn * 64 + j * 8 + tig * 2;
                float b0 = __ldg(sBias[0] + col);
                float b1 = __ldg(sBias[0] + col + 1);
                for (int s = 1; s < ns; s++) {
                    b0 += sW[s] * __ldg(sBias[s] + col);
                    b1 += sW[s] * __ldg(sBias[s] + col + 1);
                }
                float2 v0 = make_float2(c[i][j][0] + b0, c[i][j][1] + b1);
                float2 v1 = make_float2(c[i][j][2] + b0, c[i][j][3] + b1);
                *reinterpret_cast<float2*>(fout + (size_t)r0i * DD + col) = v0;
                *reinterpret_cast<float2*>(fout + (size_t)(r0i + 8) * DD + col) = v1;
            }
        }
    }
}

// ---------------- launch ----------------
extern "C" void kernel_launch(void* const* d_in, const int* in_sizes, int n_in,
                              void* d_out, int out_size)
{
    (void)in_sizes; (void)n_in; (void)out_size;
    const float* x         = (const float*)d_in[0];
    const float* time_cond = (const float*)d_in[1];
    const float* gate_w    = (const float*)d_in[2];
    const float* gate_b    = (const float*)d_in[3];
    const float* time_w    = (const float*)d_in[4];
    const float* time_b    = (const float*)d_in[5];
    const float* ew1       = (const float*)d_in[6];
    const float* eb1       = (const float*)d_in[7];
    const float* ew2       = (const float*)d_in[8];
    const float* eb2       = (const float*)d_in[9];
    const float* sw1       = (const float*)d_in[10];
    const float* sb1       = (const float*)d_in[11];
    const float* sw2       = (const float*)d_in[12];
    const float* sb2       = (const float*)d_in[13];
    float* out = (float*)d_out;

    cudaFuncSetAttribute(k_mma<0>, cudaFuncAttributeMaxDynamicSharedMemorySize, GEMM_SMEM);
    cudaFuncSetAttribute(k_mma<1>, cudaFuncAttributeMaxDynamicSharedMemorySize, GEMM_SMEM);

    // 1) all conversions in one launch:
    //    grid.x = 4096 blocks (covers 128x32 transpose tiling for each matrix),
    //    z = 0 (x convert) + 10 weight slices
    k_conv<<<dim3(4096, 1, 2 * NE + 3), dim3(32, 8)>>>(x, ew1, sw1, ew2, sw2);
    // 2) gating
    k_stageA<<<dim3(8, 6), 256>>>(x);
    k_gate<<<8, 256>>>(gate_w, gate_b, time_cond, time_w, time_b);
    // 3) GEMM1 (launch #4 -> profiled): shared + 4 experts; inactive tiles exit
    k_mma<0><<<dim3(MT / 128, HH / 128, 5), 256, GEMM_SMEM>>>(sb1, eb1, nullptr);
    // 4) GEMM2: fused accumulation over active segments, single write of out
    k_mma<1><<<dim3(MT / 128, DD / 128, 1), 256, GEMM_SMEM>>>(sb2, eb2, out);
}

// round 8
// speedup vs baseline: 1.2549x; 1.0968x over previous
#include <cuda_runtime.h>
#include <cuda_fp16.h>
#include <cstdint>

#define DD 1024
#define HH 4096
#define NB 8
#define LL 768
#define MT 6144   // NB*LL
#define NE 4

#define KCH 64               // K halfs per chunk (128B rows)
#define SS 3                 // pipeline stages
#define TILE_BYTES 16384     // 128 rows x 128B
#define STG_BYTES 32768      // A tile + B tile
#define GEMM_SMEM (SS * STG_BYTES)   // 96 KB -> 2 CTAs/SM

// ---------------- scratch (device globals; no allocation) ----------------
__device__ __align__(256) __half g_Xh[(size_t)MT * DD];
__device__ __align__(256) __half g_W1e[(size_t)NE * HH * DD];  // W1^T per expert: [H][D]
__device__ __align__(256) __half g_W2e[(size_t)NE * DD * HH];  // W2^T per expert: [D][H]
__device__ __align__(256) __half g_W1s[(size_t)HH * DD];       // sw1^T
__device__ __align__(256) __half g_W2s[(size_t)DD * HH];       // sw2^T
__device__ __align__(256) __half g_H[(size_t)5 * MT * HH];     // [shared, e0..e3] hidden
__device__ __align__(256) float  g_P[(size_t)5 * MT * DD];     // GEMM2 partials per segment
__device__ float  g_partial[NB * 6 * DD];
__device__ float  g_wbe[NB * NE];

// ---------------- helpers ----------------
__device__ __forceinline__ uint32_t smem_u32(const void* p) {
    uint32_t a;
    asm("{ .reg .u64 t; cvta.to.shared.u64 t, %1; cvt.u32.u64 %0, t; }" : "=r"(a) : "l"(p));
    return a;
}
__device__ __forceinline__ void cp_async16(void* smem, const void* gmem) {
    unsigned s = (unsigned)__cvta_generic_to_shared(smem);
    asm volatile("cp.async.cg.shared.global [%0], [%1], 16;\n" :: "r"(s), "l"(gmem) : "memory");
}
__device__ __forceinline__ void cp_commit() { asm volatile("cp.async.commit_group;\n" ::: "memory"); }

__device__ __forceinline__ void ldm4(uint32_t* r, uint32_t addr) {
    asm volatile("ldmatrix.sync.aligned.m8n8.x4.shared.b16 {%0,%1,%2,%3}, [%4];"
        : "=r"(r[0]), "=r"(r[1]), "=r"(r[2]), "=r"(r[3]) : "r"(addr));
}
__device__ __forceinline__ void mma16816(float* c, const uint32_t* a, const uint32_t* b) {
    asm volatile(
        "mma.sync.aligned.m16n8k16.row.col.f32.f16.f16.f32 "
        "{%0,%1,%2,%3}, {%4,%5,%6,%7}, {%8,%9}, {%0,%1,%2,%3};"
        : "+f"(c[0]), "+f"(c[1]), "+f"(c[2]), "+f"(c[3])
        : "r"(a[0]), "r"(a[1]), "r"(a[2]), "r"(a[3]), "r"(b[0]), "r"(b[1]));
}

__device__ __forceinline__ float gelu_t(float v) {
    float c = v + 0.044715f * v * v * v;
    return 0.5f * v * (1.f + tanhf(0.7978845608028654f * c));
}

// per-M-tile weight: batch gating weight x third-mask; exact 0 => skip tile
__device__ __forceinline__ float tile_weight(int expert, int bm) {
    if (expert < 0) return 1.f;
    int b = bm / 6;             // 6 tiles of 128 tokens per batch
    int third = (bm % 6) >> 1;  // 0 head, 1 wrist, 2 proprio
    if (expert == 1 && third == 1) return 0.f;
    if (expert == 2 && third == 0) return 0.f;
    return g_wbe[b * NE + expert];
}

// ---------------- merged conversion kernel ----------------
__global__ void k_conv(const float* __restrict__ x,
                       const float* __restrict__ ew1, const float* __restrict__ sw1,
                       const float* __restrict__ ew2, const float* __restrict__ sw2)
{
    int z = blockIdx.z;
    if (z == 0) {
        int n4 = MT * DD / 4;
        int stride = gridDim.x * blockDim.x * blockDim.y;
        int tid = (threadIdx.y * blockDim.x + threadIdx.x) + blockIdx.x * (blockDim.x * blockDim.y);
        for (int i = tid; i < n4; i += stride) {
            float4 v = reinterpret_cast<const float4*>(x)[i];
            __half2* d2 = reinterpret_cast<__half2*>(g_Xh) + (size_t)i * 2;
            d2[0] = __floats2half2_rn(v.x, v.y);
            d2[1] = __floats2half2_rn(v.z, v.w);
        }
        return;
    }
    const float* src;
    __half* dst;
    int R, C;
    if (z <= NE + 1) {                 // W1 family: [D,H] -> [H,D]
        R = DD; C = HH;
        if (z <= NE) { src = ew1 + (size_t)(z - 1) * R * C; dst = g_W1e + (size_t)(z - 1) * R * C; }
        else         { src = sw1; dst = g_W1s; }
    } else {                           // W2 family: [H,D] -> [D,H]
        R = HH; C = DD;
        int e = z - NE - 2;
        if (e < NE) { src = ew2 + (size_t)e * R * C; dst = g_W2e + (size_t)e * R * C; }
        else        { src = sw2; dst = g_W2s; }
    }
    int nCB = C / 32;
    int bx = blockIdx.x % nCB;
    int by = blockIdx.x / nCB;
    if (by >= R / 32) return;
    __shared__ float t[32][33];
    int c0 = bx * 32, r0 = by * 32;
    int tx = threadIdx.x, ty = threadIdx.y;
    #pragma unroll
    for (int j = 0; j < 32; j += 8)
        t[ty + j][tx] = src[(size_t)(r0 + ty + j) * C + c0 + tx];
    __syncthreads();
    #pragma unroll
    for (int j = 0; j < 32; j += 8)
        dst[(size_t)(c0 + ty + j) * R + r0 + tx] = __float2half(t[tx][ty + j]);
}

// ---------------- gating stage A ----------------
__global__ void k_stageA(const float* __restrict__ x) {
    int b = blockIdx.x, c = blockIdx.y, t = threadIdx.x;
    const float* base = x + ((size_t)(b * LL + c * 128)) * DD;
    for (int d = t; d < DD; d += 256) {
        float s = 0.f;
        #pragma unroll 4
        for (int l = 0; l < 128; ++l) s += base[(size_t)l * DD + d];
        g_partial[(b * 6 + c) * DD + d] = s;
    }
}

// ---------------- gating stage B ----------------
__global__ void k_gate(const float* __restrict__ gate_w, const float* __restrict__ gate_b,
                       const float* __restrict__ time_cond, const float* __restrict__ time_w,
                       const float* __restrict__ time_b)
{
    int b = blockIdx.x, t = threadIdx.x;
    __shared__ float red[12][256];
    float acc[12];
    #pragma unroll
    for (int k = 0; k < 12; k++) acc[k] = 0.f;
    for (int d = t; d < DD; d += 256) {
        float h = g_partial[(b*6+0)*DD+d] + g_partial[(b*6+1)*DD+d];
        float w = g_partial[(b*6+2)*DD+d] + g_partial[(b*6+3)*DD+d];
        float p = g_partial[(b*6+4)*DD+d] + g_partial[(b*6+5)*DD+d];
        float full = (h + w + p) * (1.f / 768.f);
        float hp   = (h + p) * (1.f / 512.f);
        float wp   = (w + p) * (1.f / 512.f);
        #pragma unroll
        for (int e = 0; e < 4; e++)
            acc[e] += full * gate_w[d*4+e] + hp * gate_w[(DD+d)*4+e] + wp * gate_w[(2*DD+d)*4+e];
        float tc = time_cond[b * DD + d];
        float s  = tc / (1.f + expf(-tc));   // silu
        #pragma unroll
        for (int j = 0; j < 8; j++) acc[4 + j] += s * time_w[d*8 + j];
    }
    #pragma unroll
    for (int k = 0; k < 12; k++) red[k][t] = acc[k];
    __syncthreads();
    for (int s = 128; s > 0; s >>= 1) {
        if (t < s) {
            #pragma unroll
            for (int k = 0; k < 12; k++) red[k][t] += red[k][t + s];
        }
        __syncthreads();
    }
    if (t == 0) {
        float logit[4], prob[4];
        #pragma unroll
        for (int e = 0; e < 4; e++) {
            float sc = red[4 + e][0] + time_b[e];
            float sh = red[8 + e][0] + time_b[4 + e];
            logit[e] = (red[e][0] + gate_b[e]) * (1.f + sc) + sh;
        }
        float mx = fmaxf(fmaxf(logit[0], logit[1]), fmaxf(logit[2], logit[3]));
        float sum = 0.f;
        for (int e = 0; e < 4; e++) { prob[e] = expf(logit[e] - mx); sum += prob[e]; }
        for (int e = 0; e < 4; e++) prob[e] /= sum;
        int i1 = 0;
        for (int e = 1; e < 4; e++) if (prob[e] > prob[i1]) i1 = e;
        int i2 = -1;
        for (int e = 0; e < 4; e++) if (e != i1 && (i2 < 0 || prob[e] > prob[i2])) i2 = e;
        float denom = prob[i1] + prob[i2] + 1e-8f;
        #pragma unroll
        for (int e = 0; e < 4; e++) g_wbe[b * NE + e] = 0.f;
        g_wbe[b * NE + i1] = prob[i1] / denom;
        g_wbe[b * NE + i2] = prob[i2] / denom;
    }
}

// ---------------- fused mma.sync GEMM (8 warps, warp tile 32x64) ----------------
// MODE 0 (GEMM1): z=0 shared, 1..4 experts. H[z] = w * gelu(X@W1[z] + b1[z])   (N=HH, K=DD)
// MODE 1 (GEMM2): z=0 shared, 1..4 experts. P[z] = H[z] @ W2[z]  (raw fp32, N=DD, K=HH)
template<int MODE>
__global__ void __launch_bounds__(256, 2) k_mma(
    const float* __restrict__ b_sh, const float* __restrict__ b_ex)
{
    constexpr int Ks = (MODE == 0) ? DD : HH;
    constexpr int N  = (MODE == 0) ? HH : DD;
    constexpr int nch = Ks / KCH;

    int bm = blockIdx.x, bn = blockIdx.y, z = blockIdx.z;
    float w = tile_weight(z - 1, bm);
    if (w == 0.f) return;

    const __half* A;
    const __half* B;
    const float* bias;
    if (MODE == 0) {
        A = g_Xh;
        B = (z == 0) ? g_W1s : (g_W1e + (size_t)(z - 1) * HH * DD);
        bias = (z == 0) ? b_sh : (b_ex + (size_t)(z - 1) * HH);
    } else {
        A = g_H + (size_t)z * MT * HH;
        B = (z == 0) ? g_W2s : (g_W2e + (size_t)(z - 1) * DD * HH);
        bias = nullptr;
    }
    __half* hout = g_H + (size_t)z * MT * HH;
    float*  pout = g_P + (size_t)z * MT * DD;

    extern __shared__ __align__(128) char smem[];
    uint32_t sbase = smem_u32(smem);
    int tid = threadIdx.x, lane = tid & 31, wid = tid >> 5;
    int wm = wid & 3, wn = wid >> 2;          // 4x2 warps, warp tile 32x64
    int m0 = bm * 128, n0 = bn * 128;

    auto issue = [&](int it, int slot) {
        int koff = it * KCH;
        const __half* Ab = A + koff;
        const __half* Bb = B + koff;
        char* st = smem + slot * STG_BYTES;
        #pragma unroll
        for (int i = 0; i < 4; i++) {
            int idx = tid + i * 256;
            int r = idx >> 3, c8 = idx & 7;
            uint32_t off = (uint32_t)(r * 128 + c8 * 16);
            off ^= (off >> 3) & 0x70;
            cp_async16(st + off, Ab + (size_t)(m0 + r) * Ks + c8 * 8);
        }
        #pragma unroll
        for (int i = 0; i < 4; i++) {
            int idx = tid + i * 256;
            int r = idx >> 3, c8 = idx & 7;
            uint32_t off = (uint32_t)(r * 128 + c8 * 16);
            off ^= (off >> 3) & 0x70;
            cp_async16(st + TILE_BYTES + off, Bb + (size_t)(n0 + r) * Ks + c8 * 8);
        }
        cp_commit();
    };

    float c[2][8][4];
    #pragma unroll
    for (int i = 0; i < 2; i++)
        #pragma unroll
        for (int j = 0; j < 8; j++)
            #pragma unroll
            for (int q = 0; q < 4; q++) c[i][j][q] = 0.f;

    issue(0, 0);
    issue(1, 1);

    for (int it = 0; it < nch; ++it) {
        if (it + 1 < nch) asm volatile("cp.async.wait_group 1;" ::: "memory");
        else              asm volatile("cp.async.wait_group 0;" ::: "memory");
        __syncthreads();
        if (it + 2 < nch) issue(it + 2, (it + 2) % SS);

        uint32_t sAb = sbase + (it % SS) * STG_BYTES;
        uint32_t sBb = sAb + TILE_BYTES;
        #pragma unroll
        for (int kk = 0; kk < 4; kk++) {
            uint32_t a[2][4];
            #pragma unroll
            for (int i = 0; i < 2; i++) {
                int row = wm * 32 + i * 16 + (lane & 15);
                uint32_t off = (uint32_t)(row * 128 + kk * 32 + ((lane >> 4) & 1) * 16);
                off ^= (off >> 3) & 0x70;
                ldm4(a[i], sAb + off);
            }
            uint32_t b[8][2];
            #pragma unroll
            for (int jp = 0; jp < 4; jp++) {
                int n = wn * 64 + jp * 16 + ((lane >> 4) & 1) * 8 + (lane & 7);
                uint32_t off = (uint32_t)(n * 128 + kk * 32 + ((lane >> 3) & 1) * 16);
                off ^= (off >> 3) & 0x70;
                uint32_t r4[4];
                ldm4(r4, sBb + off);
                b[2 * jp][0] = r4[0]; b[2 * jp][1] = r4[1];
                b[2 * jp + 1][0] = r4[2]; b[2 * jp + 1][1] = r4[3];
            }
            #pragma unroll
            for (int i = 0; i < 2; i++)
                #pragma unroll
                for (int j = 0; j < 8; j++)
                    mma16816(c[i][j], a[i], b[j]);
        }
    }

    // ---- epilogue (register-direct) ----
    int gid = lane >> 2, tig = lane & 3;
    if (MODE == 0) {
        #pragma unroll
        for (int i = 0; i < 2; i++) {
            int r0i = m0 + wm * 32 + i * 16 + gid;
            #pragma unroll
            for (int j = 0; j < 8; j++) {
                int col = n0 + wn * 64 + j * 8 + tig * 2;
                float b0 = __ldg(bias + col);
                float b1 = __ldg(bias + col + 1);
                __half2 h0 = __floats2half2_rn(w * gelu_t(c[i][j][0] + b0),
                                               w * gelu_t(c[i][j][1] + b1));
                __half2 h1 = __floats2half2_rn(w * gelu_t(c[i][j][2] + b0),
                                               w * gelu_t(c[i][j][3] + b1));
                *reinterpret_cast<__half2*>(hout + (size_t)r0i * HH + col) = h0;
                *reinterpret_cast<__half2*>(hout + (size_t)(r0i + 8) * HH + col) = h1;
            }
        }
    } else {
        #pragma unroll
        for (int i = 0; i < 2; i++) {
            int r0i = m0 + wm * 32 + i * 16 + gid;
            #pragma unroll
            for (int j = 0; j < 8; j++) {
                int col = n0 + wn * 64 + j * 8 + tig * 2;
                *reinterpret_cast<float2*>(pout + (size_t)r0i * DD + col) =
                    make_float2(c[i][j][0], c[i][j][1]);
                *reinterpret_cast<float2*>(pout + (size_t)(r0i + 8) * DD + col) =
                    make_float2(c[i][j][2], c[i][j][3]);
            }
        }
    }
}

// ---------------- reduce: out = P_sh + sum_e 1[w>0] P_e + b_sh + sum_e w*mask*b2_e ----------------
__global__ void k_reduce(const float* __restrict__ b_sh, const float* __restrict__ b_ex,
                         float* __restrict__ out)
{
    int bm = blockIdx.x;                 // 128-row block
    int bn = blockIdx.y;                 // 128-col block
    float we[NE];
    #pragma unroll
    for (int e = 0; e < NE; e++) we[e] = tile_weight(e, bm);

    int tid = threadIdx.x;               // 256 threads
    size_t base = (size_t)bm * 128 * DD + bn * 128;
    // 128 rows x 128 cols, float4: 32 f4 per row, 4096 f4 per block, 16 per thread
    for (int q = tid; q < 4096; q += 256) {
        int r = q >> 5;
        int c4 = (q & 31) << 2;
        size_t off = base + (size_t)r * DD + c4;
        int col = bn * 128 + c4;
        float4 acc = *reinterpret_cast<const float4*>(g_P + off);           // shared partial
        float4 bs = *reinterpret_cast<const float4*>(b_sh + col);
        acc.x += bs.x; acc.y += bs.y; acc.z += bs.z; acc.w += bs.w;
        #pragma unroll
        for (int e = 0; e < NE; e++) {
            if (we[e] > 0.f) {
                float4 p = *reinterpret_cast<const float4*>(g_P + (size_t)(e + 1) * MT * DD + off);
                float4 be = *reinterpret_cast<const float4*>(b_ex + (size_t)e * DD + col);
                acc.x += p.x + we[e] * be.x;
                acc.y += p.y + we[e] * be.y;
                acc.z += p.z + we[e] * be.z;
                acc.w += p.w + we[e] * be.w;
            }
        }
        *reinterpret_cast<float4*>(out + off) = acc;
    }
}

// ---------------- launch ----------------
extern "C" void kernel_launch(void* const* d_in, const int* in_sizes, int n_in,
                              void* d_out, int out_size)
{
    (void)in_sizes; (void)n_in; (void)out_size;
    const float* x         = (const float*)d_in[0];
    const float* time_cond = (const float*)d_in[1];
    const float* gate_w    = (const float*)d_in[2];
    const float* gate_b    = (const float*)d_in[3];
    const float* time_w    = (const float*)d_in[4];
    const float* time_b    = (const float*)d_in[5];
    const float* ew1       = (const float*)d_in[6];
    const float* eb1       = (const float*)d_in[7];
    const float* ew2       = (const float*)d_in[8];
    const float* eb2       = (const float*)d_in[9];
    const float* sw1       = (const float*)d_in[10];
    const float* sb1       = (const float*)d_in[11];
    const float* sw2       = (const float*)d_in[12];
    const float* sb2       = (const float*)d_in[13];
    float* out = (float*)d_out;

    cudaFuncSetAttribute(k_mma<0>, cudaFuncAttributeMaxDynamicSharedMemorySize, GEMM_SMEM);
    cudaFuncSetAttribute(k_mma<1>, cudaFuncAttributeMaxDynamicSharedMemorySize, GEMM_SMEM);

    // 1) all conversions (x + 10 weight slices) in one launch
    k_conv<<<dim3(4096, 1, 2 * NE + 3), dim3(32, 8)>>>(x, ew1, sw1, ew2, sw2);
    // 2) gating
    k_stageA<<<dim3(8, 6), 256>>>(x);
    k_gate<<<8, 256>>>(gate_w, gate_b, time_cond, time_w, time_b);
    // 3) GEMM1: shared + 4 experts; inactive tiles exit
    k_mma<0><<<dim3(MT / 128, HH / 128, 5), 256, GEMM_SMEM>>>(sb1, eb1);
    // 4) GEMM2 split by segment: each z writes its own fp32 partial
    k_mma<1><<<dim3(MT / 128, DD / 128, 5), 256, GEMM_SMEM>>>(sb2, eb2);
    // 5) combine partials + biases into out (single deterministic write)
    k_reduce<<<dim3(MT / 128, DD / 128), 256>>>(sb2, eb2, out);
}

// round 9
// speedup vs baseline: 1.2631x; 1.0065x over previous
#include <cuda_runtime.h>
#include <cuda_fp16.h>
#include <cstdint>

#define DD 1024
#define HH 4096
#define NB 8
#define LL 768
#define MT 6144   // NB*LL
#define NE 4

#define KCH 64               // K halfs per chunk (128B rows)
#define SS 3                 // pipeline stages
#define TILE_BYTES 16384     // 128 rows x 128B
#define STG_BYTES 32768      // A tile + B tile
#define GEMM_SMEM (SS * STG_BYTES)   // 96 KB -> 2 CTAs/SM

// ---------------- scratch (device globals; no allocation) ----------------
__device__ __align__(256) __half g_Xh[(size_t)MT * DD];
__device__ __align__(256) __half g_W1e[(size_t)NE * HH * DD];  // W1^T per expert: [H][D]
__device__ __align__(256) __half g_W2e[(size_t)NE * DD * HH];  // W2^T per expert: [D][H]
__device__ __align__(256) __half g_W1s[(size_t)HH * DD];       // sw1^T
__device__ __align__(256) __half g_W2s[(size_t)DD * HH];       // sw2^T
__device__ __align__(256) __half g_H[(size_t)5 * MT * HH];     // [shared, e0..e3] hidden
__device__ __align__(256) float  g_P[(size_t)2 * MT * DD];     // GEMM2 split-K partials
__device__ float  g_partial[NB * 6 * DD];
__device__ float  g_wbe[NB * NE];

// ---------------- helpers ----------------
__device__ __forceinline__ uint32_t smem_u32(const void* p) {
    uint32_t a;
    asm("{ .reg .u64 t; cvta.to.shared.u64 t, %1; cvt.u32.u64 %0, t; }" : "=r"(a) : "l"(p));
    return a;
}
__device__ __forceinline__ void cp_async16(void* smem, const void* gmem) {
    unsigned s = (unsigned)__cvta_generic_to_shared(smem);
    asm volatile("cp.async.cg.shared.global [%0], [%1], 16;\n" :: "r"(s), "l"(gmem) : "memory");
}
__device__ __forceinline__ void cp_commit() { asm volatile("cp.async.commit_group;\n" ::: "memory"); }

__device__ __forceinline__ void ldm4(uint32_t* r, uint32_t addr) {
    asm volatile("ldmatrix.sync.aligned.m8n8.x4.shared.b16 {%0,%1,%2,%3}, [%4];"
        : "=r"(r[0]), "=r"(r[1]), "=r"(r[2]), "=r"(r[3]) : "r"(addr));
}
__device__ __forceinline__ void mma16816(float* c, const uint32_t* a, const uint32_t* b) {
    asm volatile(
        "mma.sync.aligned.m16n8k16.row.col.f32.f16.f16.f32 "
        "{%0,%1,%2,%3}, {%4,%5,%6,%7}, {%8,%9}, {%0,%1,%2,%3};"
        : "+f"(c[0]), "+f"(c[1]), "+f"(c[2]), "+f"(c[3])
        : "r"(a[0]), "r"(a[1]), "r"(a[2]), "r"(a[3]), "r"(b[0]), "r"(b[1]));
}

__device__ __forceinline__ float gelu_t(float v) {
    float c = v + 0.044715f * v * v * v;
    return 0.5f * v * (1.f + tanhf(0.7978845608028654f * c));
}

// per-M-tile weight: batch gating weight x third-mask; exact 0 => skip tile
__device__ __forceinline__ float tile_weight(int expert, int bm) {
    if (expert < 0) return 1.f;
    int b = bm / 6;             // 6 tiles of 128 tokens per batch
    int third = (bm % 6) >> 1;  // 0 head, 1 wrist, 2 proprio
    if (expert == 1 && third == 1) return 0.f;
    if (expert == 2 && third == 0) return 0.f;
    return g_wbe[b * NE + expert];
}

// ---------------- merged conversion + stageA kernel ----------------
// z == 0          : x fp32 -> fp16 into g_Xh
// z in 1..NE      : ew1 expert [D,H] -> [H,D]
// z == NE+1       : sw1 -> g_W1s
// z in NE+2..2NE+1: ew2 expert [H,D] -> [D,H]
// z == 2NE+2      : sw2 -> g_W2s
// z == 2NE+3      : gating stage A partial sums (blocks 0..47)
__global__ void k_conv(const float* __restrict__ x,
                       const float* __restrict__ ew1, const float* __restrict__ sw1,
                       const float* __restrict__ ew2, const float* __restrict__ sw2)
{
    int z = blockIdx.z;
    int ltid = threadIdx.y * 32 + threadIdx.x;   // 0..255
    if (z == 0) {
        int n4 = MT * DD / 4;
        int stride = gridDim.x * 256;
        for (int i = ltid + blockIdx.x * 256; i < n4; i += stride) {
            float4 v = reinterpret_cast<const float4*>(x)[i];
            __half2* d2 = reinterpret_cast<__half2*>(g_Xh) + (size_t)i * 2;
            d2[0] = __floats2half2_rn(v.x, v.y);
            d2[1] = __floats2half2_rn(v.z, v.w);
        }
        return;
    }
    if (z == 2 * NE + 3) {
        // gating stage A: blocks 0..47 -> (batch, chunk)
        if (blockIdx.x >= NB * 6) return;
        int b = blockIdx.x / 6, c = blockIdx.x % 6;
        const float* base = x + ((size_t)(b * LL + c * 128)) * DD;
        for (int d = ltid; d < DD; d += 256) {
            float s = 0.f;
            #pragma unroll 4
            for (int l = 0; l < 128; ++l) s += base[(size_t)l * DD + d];
            g_partial[(b * 6 + c) * DD + d] = s;
        }
        return;
    }
    const float* src;
    __half* dst;
    int R, C;
    if (z <= NE + 1) {                 // W1 family: [D,H] -> [H,D]
        R = DD; C = HH;
        if (z <= NE) { src = ew1 + (size_t)(z - 1) * R * C; dst = g_W1e + (size_t)(z - 1) * R * C; }
        else         { src = sw1; dst = g_W1s; }
    } else {                           // W2 family: [H,D] -> [D,H]
        R = HH; C = DD;
        int e = z - NE - 2;
        if (e < NE) { src = ew2 + (size_t)e * R * C; dst = g_W2e + (size_t)e * R * C; }
        else        { src = sw2; dst = g_W2s; }
    }
    int nCB = C / 32;
    int bx = blockIdx.x % nCB;
    int by = blockIdx.x / nCB;
    if (by >= R / 32) return;
    __shared__ float t[32][33];
    int c0 = bx * 32, r0 = by * 32;
    int tx = threadIdx.x, ty = threadIdx.y;
    #pragma unroll
    for (int j = 0; j < 32; j += 8)
        t[ty + j][tx] = src[(size_t)(r0 + ty + j) * C + c0 + tx];
    __syncthreads();
    #pragma unroll
    for (int j = 0; j < 32; j += 8)
        dst[(size_t)(c0 + ty + j) * R + r0 + tx] = __float2half(t[tx][ty + j]);
}

// ---------------- gating stage B ----------------
__global__ void k_gate(const float* __restrict__ gate_w, const float* __restrict__ gate_b,
                       const float* __restrict__ time_cond, const float* __restrict__ time_w,
                       const float* __restrict__ time_b)
{
    int b = blockIdx.x, t = threadIdx.x;
    __shared__ float red[12][256];
    float acc[12];
    #pragma unroll
    for (int k = 0; k < 12; k++) acc[k] = 0.f;
    for (int d = t; d < DD; d += 256) {
        float h = g_partial[(b*6+0)*DD+d] + g_partial[(b*6+1)*DD+d];
        float w = g_partial[(b*6+2)*DD+d] + g_partial[(b*6+3)*DD+d];
        float p = g_partial[(b*6+4)*DD+d] + g_partial[(b*6+5)*DD+d];
        float full = (h + w + p) * (1.f / 768.f);
        float hp   = (h + p) * (1.f / 512.f);
        float wp   = (w + p) * (1.f / 512.f);
        #pragma unroll
        for (int e = 0; e < 4; e++)
            acc[e] += full * gate_w[d*4+e] + hp * gate_w[(DD+d)*4+e] + wp * gate_w[(2*DD+d)*4+e];
        float tc = time_cond[b * DD + d];
        float s  = tc / (1.f + expf(-tc));   // silu
        #pragma unroll
        for (int j = 0; j < 8; j++) acc[4 + j] += s * time_w[d*8 + j];
    }
    #pragma unroll
    for (int k = 0; k < 12; k++) red[k][t] = acc[k];
    __syncthreads();
    for (int s = 128; s > 0; s >>= 1) {
        if (t < s) {
            #pragma unroll
            for (int k = 0; k < 12; k++) red[k][t] += red[k][t + s];
        }
        __syncthreads();
    }
    if (t == 0) {
        float logit[4], prob[4];
        #pragma unroll
        for (int e = 0; e < 4; e++) {
            float sc = red[4 + e][0] + time_b[e];
            float sh = red[8 + e][0] + time_b[4 + e];
            logit[e] = (red[e][0] + gate_b[e]) * (1.f + sc) + sh;
        }
        float mx = fmaxf(fmaxf(logit[0], logit[1]), fmaxf(logit[2], logit[3]));
        float sum = 0.f;
        for (int e = 0; e < 4; e++) { prob[e] = expf(logit[e] - mx); sum += prob[e]; }
        for (int e = 0; e < 4; e++) prob[e] /= sum;
        int i1 = 0;
        for (int e = 1; e < 4; e++) if (prob[e] > prob[i1]) i1 = e;
        int i2 = -1;
        for (int e = 0; e < 4; e++) if (e != i1 && (i2 < 0 || prob[e] > prob[i2])) i2 = e;
        float denom = prob[i1] + prob[i2] + 1e-8f;
        #pragma unroll
        for (int e = 0; e < 4; e++) g_wbe[b * NE + e] = 0.f;
        g_wbe[b * NE + i1] = prob[i1] / denom;
        g_wbe[b * NE + i2] = prob[i2] / denom;
    }
}

// ---------------- GEMM1 (8 warps, warp tile 32x64): H[z] = w*gelu(X@W1[z] + b1[z]) ----------------
__global__ void __launch_bounds__(256, 2) k_mma1(
    const float* __restrict__ b_sh, const float* __restrict__ b_ex)
{
    constexpr int Ks = DD;
    constexpr int nch = Ks / KCH;

    int bm = blockIdx.x, bn = blockIdx.y, z = blockIdx.z;
    float w = tile_weight(z - 1, bm);
    if (w == 0.f) return;

    const __half* A = g_Xh;
    const __half* B = (z == 0) ? g_W1s : (g_W1e + (size_t)(z - 1) * HH * DD);
    const float* bias = (z == 0) ? b_sh : (b_ex + (size_t)(z - 1) * HH);
    __half* hout = g_H + (size_t)z * MT * HH;

    extern __shared__ __align__(128) char smem[];
    uint32_t sbase = smem_u32(smem);
    int tid = threadIdx.x, lane = tid & 31, wid = tid >> 5;
    int wm = wid & 3, wn = wid >> 2;
    int m0 = bm * 128, n0 = bn * 128;

    auto issue = [&](int it, int slot) {
        int koff = it * KCH;
        const __half* Ab = A + koff;
        const __half* Bb = B + koff;
        char* st = smem + slot * STG_BYTES;
        #pragma unroll
        for (int i = 0; i < 4; i++) {
            int idx = tid + i * 256;
            int r = idx >> 3, c8 = idx & 7;
            uint32_t off = (uint32_t)(r * 128 + c8 * 16);
            off ^= (off >> 3) & 0x70;
            cp_async16(st + off, Ab + (size_t)(m0 + r) * Ks + c8 * 8);
        }
        #pragma unroll
        for (int i = 0; i < 4; i++) {
            int idx = tid + i * 256;
            int r = idx >> 3, c8 = idx & 7;
            uint32_t off = (uint32_t)(r * 128 + c8 * 16);
            off ^= (off >> 3) & 0x70;
            cp_async16(st + TILE_BYTES + off, Bb + (size_t)(n0 + r) * Ks + c8 * 8);
        }
        cp_commit();
    };

    float c[2][8][4];
    #pragma unroll
    for (int i = 0; i < 2; i++)
        #pragma unroll
        for (int j = 0; j < 8; j++)
            #pragma unroll
            for (int q = 0; q < 4; q++) c[i][j][q] = 0.f;

    issue(0, 0);
    issue(1, 1);

    for (int it = 0; it < nch; ++it) {
        if (it + 1 < nch) asm volatile("cp.async.wait_group 1;" ::: "memory");
        else              asm volatile("cp.async.wait_group 0;" ::: "memory");
        __syncthreads();
        if (it + 2 < nch) issue(it + 2, (it + 2) % SS);

        uint32_t sAb = sbase + (it % SS) * STG_BYTES;
        uint32_t sBb = sAb + TILE_BYTES;
        #pragma unroll
        for (int kk = 0; kk < 4; kk++) {
            uint32_t a[2][4];
            #pragma unroll
            for (int i = 0; i < 2; i++) {
                int row = wm * 32 + i * 16 + (lane & 15);
                uint32_t off = (uint32_t)(row * 128 + kk * 32 + ((lane >> 4) & 1) * 16);
                off ^= (off >> 3) & 0x70;
                ldm4(a[i], sAb + off);
            }
            uint32_t b[8][2];
            #pragma unroll
            for (int jp = 0; jp < 4; jp++) {
                int n = wn * 64 + jp * 16 + ((lane >> 4) & 1) * 8 + (lane & 7);
                uint32_t off = (uint32_t)(n * 128 + kk * 32 + ((lane >> 3) & 1) * 16);
                off ^= (off >> 3) & 0x70;
                uint32_t r4[4];
                ldm4(r4, sBb + off);
                b[2 * jp][0] = r4[0]; b[2 * jp][1] = r4[1];
                b[2 * jp + 1][0] = r4[2]; b[2 * jp + 1][1] = r4[3];
            }
            #pragma unroll
            for (int i = 0; i < 2; i++)
                #pragma unroll
                for (int j = 0; j < 8; j++)
                    mma16816(c[i][j], a[i], b[j]);
        }
    }

    int gid = lane >> 2, tig = lane & 3;
    #pragma unroll
    for (int i = 0; i < 2; i++) {
        int r0i = m0 + wm * 32 + i * 16 + gid;
        #pragma unroll
        for (int j = 0; j < 8; j++) {
            int col = n0 + wn * 64 + j * 8 + tig * 2;
            float b0 = __ldg(bias + col);
            float b1 = __ldg(bias + col + 1);
            __half2 h0 = __floats2half2_rn(w * gelu_t(c[i][j][0] + b0),
                                           w * gelu_t(c[i][j][1] + b1));
            __half2 h1 = __floats2half2_rn(w * gelu_t(c[i][j][2] + b0),
                                           w * gelu_t(c[i][j][3] + b1));
            *reinterpret_cast<__half2*>(hout + (size_t)r0i * HH + col) = h0;
            *reinterpret_cast<__half2*>(hout + (size_t)(r0i + 8) * HH + col) = h1;
        }
    }
}

// ---------------- GEMM2: split-K(2) x segment-concat. P[zk] = sum over segs, K-half zk ----------------
__global__ void __launch_bounds__(256, 2) k_mma2()
{
    int bm = blockIdx.x, bn = blockIdx.y, zk = blockIdx.z;   // zk in {0,1}
    __shared__ const __half* sA[1 + NE];
    __shared__ const __half* sB[1 + NE];
    __shared__ int sNs;

    if (threadIdx.x == 0) {
        int ns = 0;
        sA[ns] = g_H; sB[ns] = g_W2s; ns++;
        for (int e = 0; e < NE; e++) {
            if (tile_weight(e, bm) > 0.f) {
                sA[ns] = g_H + (size_t)(e + 1) * MT * HH;
                sB[ns] = g_W2e + (size_t)e * DD * HH;
                ns++;
            }
        }
        sNs = ns;
    }
    __syncthreads();
    int ns = sNs;
    int nch = ns * 32;                  // 32 chunks = K-half (2048) per segment
    int kbase = zk * 2048;

    extern __shared__ __align__(128) char smem[];
    uint32_t sbase = smem_u32(smem);
    int tid = threadIdx.x, lane = tid & 31, wid = tid >> 5;
    int wm = wid & 3, wn = wid >> 2;
    int m0 = bm * 128, n0 = bn * 128;
    float* pout = g_P + (size_t)zk * MT * DD;

    auto issue = [&](int flat, int slot) {
        int seg = flat >> 5;
        int koff = kbase + (flat & 31) * KCH;
        const __half* Ab = sA[seg] + koff;
        const __half* Bb = sB[seg] + koff;
        char* st = smem + slot * STG_BYTES;
        #pragma unroll
        for (int i = 0; i < 4; i++) {
            int idx = tid + i * 256;
            int r = idx >> 3, c8 = idx & 7;
            uint32_t off = (uint32_t)(r * 128 + c8 * 16);
            off ^= (off >> 3) & 0x70;
            cp_async16(st + off, Ab + (size_t)(m0 + r) * HH + c8 * 8);
        }
        #pragma unroll
        for (int i = 0; i < 4; i++) {
            int idx = tid + i * 256;
            int r = idx >> 3, c8 = idx & 7;
            uint32_t off = (uint32_t)(r * 128 + c8 * 16);
            off ^= (off >> 3) & 0x70;
            cp_async16(st + TILE_BYTES + off, Bb + (size_t)(n0 + r) * HH + c8 * 8);
        }
        cp_commit();
    };

    float c[2][8][4];
    #pragma unroll
    for (int i = 0; i < 2; i++)
        #pragma unroll
        for (int j = 0; j < 8; j++)
            #pragma unroll
            for (int q = 0; q < 4; q++) c[i][j][q] = 0.f;

    issue(0, 0);
    issue(1, 1);

    for (int it = 0; it < nch; ++it) {
        if (it + 1 < nch) asm volatile("cp.async.wait_group 1;" ::: "memory");
        else              asm volatile("cp.async.wait_group 0;" ::: "memory");
        __syncthreads();
        if (it + 2 < nch) issue(it + 2, (it + 2) % SS);

        uint32_t sAb = sbase + (it % SS) * STG_BYTES;
        uint32_t sBb = sAb + TILE_BYTES;
        #pragma unroll
        for (int kk = 0; kk < 4; kk++) {
            uint32_t a[2][4];
            #pragma unroll
            for (int i = 0; i < 2; i++) {
                int row = wm * 32 + i * 16 + (lane & 15);
                uint32_t off = (uint32_t)(row * 128 + kk * 32 + ((lane >> 4) & 1) * 16);
                off ^= (off >> 3) & 0x70;
                ldm4(a[i], sAb + off);
            }
            uint32_t b[8][2];
            #pragma unroll
            for (int jp = 0; jp < 4; jp++) {
                int n = wn * 64 + jp * 16 + ((lane >> 4) & 1) * 8 + (lane & 7);
                uint32_t off = (uint32_t)(n * 128 + kk * 32 + ((lane >> 3) & 1) * 16);
                off ^= (off >> 3) & 0x70;
                uint32_t r4[4];
                ldm4(r4, sBb + off);
                b[2 * jp][0] = r4[0]; b[2 * jp][1] = r4[1];
                b[2 * jp + 1][0] = r4[2]; b[2 * jp + 1][1] = r4[3];
            }
            #pragma unroll
            for (int i = 0; i < 2; i++)
                #pragma unroll
                for (int j = 0; j < 8; j++)
                    mma16816(c[i][j], a[i], b[j]);
        }
    }

    int gid = lane >> 2, tig = lane & 3;
    #pragma unroll
    for (int i = 0; i < 2; i++) {
        int r0i = m0 + wm * 32 + i * 16 + gid;
        #pragma unroll
        for (int j = 0; j < 8; j++) {
            int col = n0 + wn * 64 + j * 8 + tig * 2;
            *reinterpret_cast<float2*>(pout + (size_t)r0i * DD + col) =
                make_float2(c[i][j][0], c[i][j][1]);
            *reinterpret_cast<float2*>(pout + (size_t)(r0i + 8) * DD + col) =
                make_float2(c[i][j][2], c[i][j][3]);
        }
    }
}

// ---------------- reduce: out = P0 + P1 + b_sh + sum_e w*mask*b2_e ----------------
__global__ void k_reduce(const float* __restrict__ b_sh, const float* __restrict__ b_ex,
                         float* __restrict__ out)
{
    int bm = blockIdx.x;                 // 128-row block
    int bn = blockIdx.y;                 // 128-col block
    float we[NE];
    #pragma unroll
    for (int e = 0; e < NE; e++) we[e] = tile_weight(e, bm);

    int tid = threadIdx.x;               // 256 threads
    size_t base = (size_t)bm * 128 * DD + bn * 128;
    for (int q = tid; q < 4096; q += 256) {
        int r = q >> 5;
        int c4 = (q & 31) << 2;
        size_t off = base + (size_t)r * DD + c4;
        int col = bn * 128 + c4;
        float4 acc = *reinterpret_cast<const float4*>(g_P + off);
        float4 p1  = *reinterpret_cast<const float4*>(g_P + (size_t)MT * DD + off);
        float4 bs  = *reinterpret_cast<const float4*>(b_sh + col);
        acc.x += p1.x + bs.x; acc.y += p1.y + bs.y;
        acc.z += p1.z + bs.z; acc.w += p1.w + bs.w;
        #pragma unroll
        for (int e = 0; e < NE; e++) {
            if (we[e] > 0.f) {
                float4 be = *reinterpret_cast<const float4*>(b_ex + (size_t)e * DD + col);
                acc.x += we[e] * be.x; acc.y += we[e] * be.y;
                acc.z += we[e] * be.z; acc.w += we[e] * be.w;
            }
        }
        *reinterpret_cast<float4*>(out + off) = acc;
    }
}

// ---------------- launch ----------------
extern "C" void kernel_launch(void* const* d_in, const int* in_sizes, int n_in,
                              void* d_out, int out_size)
{
    (void)in_sizes; (void)n_in; (void)out_size;
    const float* x         = (const float*)d_in[0];
    const float* time_cond = (const float*)d_in[1];
    const float* gate_w    = (const float*)d_in[2];
    const float* gate_b    = (const float*)d_in[3];
    const float* time_w    = (const float*)d_in[4];
    const float* time_b    = (const float*)d_in[5];
    const float* ew1       = (const float*)d_in[6];
    const float* eb1       = (const float*)d_in[7];
    const float* ew2       = (const float*)d_in[8];
    const float* eb2       = (const float*)d_in[9];
    const float* sw1       = (const float*)d_in[10];
    const float* sb1       = (const float*)d_in[11];
    const float* sw2       = (const float*)d_in[12];
    const float* sb2       = (const float*)d_in[13];
    float* out = (float*)d_out;

    cudaFuncSetAttribute(k_mma1, cudaFuncAttributeMaxDynamicSharedMemorySize, GEMM_SMEM);
    cudaFuncSetAttribute(k_mma2, cudaFuncAttributeMaxDynamicSharedMemorySize, GEMM_SMEM);

    // 1) conversions + gating stage A, one launch (z = 12 slices)
    k_conv<<<dim3(4096, 1, 2 * NE + 4), dim3(32, 8)>>>(x, ew1, sw1, ew2, sw2);
    // 2) gating stage B
    k_gate<<<8, 256>>>(gate_w, gate_b, time_cond, time_w, time_b);
    // 3) GEMM1: shared + 4 experts; inactive tiles exit
    k_mma1<<<dim3(MT / 128, HH / 128, 5), 256, GEMM_SMEM>>>(sb1, eb1);
    // 4) GEMM2: split-K(2) with in-CTA segment concat -> 2 fp32 partials
    k_mma2<<<dim3(MT / 128, DD / 128, 2), 256, GEMM_SMEM>>>();
    // 5) combine partials + biases into out (single deterministic write)
    k_reduce<<<dim3(MT / 128, DD / 128), 256>>>(sb2, eb2, out);
}

// round 10
// speedup vs baseline: 1.3232x; 1.0475x over previous
#include <cuda_runtime.h>
#include <cuda_fp16.h>
#include <cstdint>

#define DD 1024
#define HH 4096
#define NB 8
#define LL 768
#define MT 6144   // NB*LL
#define NE 4

#define KCH 64               // K halfs per chunk (128B rows)
#define SS 3                 // pipeline stages
#define TILE_BYTES 16384     // 128 rows x 128B
#define STG_BYTES 32768      // A tile + B tile
#define GEMM_SMEM (SS * STG_BYTES)   // 96 KB -> 2 CTAs/SM

// ---------------- scratch (device globals; no allocation) ----------------
__device__ __align__(256) __half g_Xh[(size_t)MT * DD];
__device__ __align__(256) __half g_W1e[(size_t)NE * HH * DD];  // W1^T per expert: [H][D]
__device__ __align__(256) __half g_W2e[(size_t)NE * DD * HH];  // W2^T per expert: [D][H]
__device__ __align__(256) __half g_W1s[(size_t)HH * DD];       // sw1^T
__device__ __align__(256) __half g_W2s[(size_t)DD * HH];       // sw2^T
__device__ __align__(256) __half g_H[(size_t)5 * MT * HH];     // [shared, e0..e3] hidden
__device__ __align__(256) float  g_P[(size_t)2 * MT * DD];     // GEMM2 split-K partials
__device__ float  g_partial[NB * 6 * DD];
__device__ float  g_wbe[NB * NE];

// ---------------- helpers ----------------
__device__ __forceinline__ uint32_t smem_u32(const void* p) {
    uint32_t a;
    asm("{ .reg .u64 t; cvta.to.shared.u64 t, %1; cvt.u32.u64 %0, t; }" : "=r"(a) : "l"(p));
    return a;
}
__device__ __forceinline__ void cp_async16(void* smem, const void* gmem) {
    unsigned s = (unsigned)__cvta_generic_to_shared(smem);
    asm volatile("cp.async.cg.shared.global [%0], [%1], 16;\n" :: "r"(s), "l"(gmem) : "memory");
}
__device__ __forceinline__ void cp_commit() { asm volatile("cp.async.commit_group;\n" ::: "memory"); }

__device__ __forceinline__ void ldm4(uint32_t* r, uint32_t addr) {
    asm volatile("ldmatrix.sync.aligned.m8n8.x4.shared.b16 {%0,%1,%2,%3}, [%4];"
        : "=r"(r[0]), "=r"(r[1]), "=r"(r[2]), "=r"(r[3]) : "r"(addr));
}
__device__ __forceinline__ void mma16816(float* c, const uint32_t* a, const uint32_t* b) {
    asm volatile(
        "mma.sync.aligned.m16n8k16.row.col.f32.f16.f16.f32 "
        "{%0,%1,%2,%3}, {%4,%5,%6,%7}, {%8,%9}, {%0,%1,%2,%3};"
        : "+f"(c[0]), "+f"(c[1]), "+f"(c[2]), "+f"(c[3])
        : "r"(a[0]), "r"(a[1]), "r"(a[2]), "r"(a[3]), "r"(b[0]), "r"(b[1]));
}

// fast GELU (tanh approx via single-instruction MUFU tanh)
__device__ __forceinline__ float gelu_t(float v) {
    float c = 0.7978845608028654f * (v + 0.044715f * v * v * v);
    float t;
    asm("tanh.approx.f32 %0, %1;" : "=f"(t) : "f"(c));
    return 0.5f * v * (1.f + t);
}

// per-M-tile weight: batch gating weight x third-mask; exact 0 => skip tile
__device__ __forceinline__ float tile_weight(int expert, int bm) {
    if (expert < 0) return 1.f;
    int b = bm / 6;             // 6 tiles of 128 tokens per batch
    int third = (bm % 6) >> 1;  // 0 head, 1 wrist, 2 proprio
    if (expert == 1 && third == 1) return 0.f;
    if (expert == 2 && third == 0) return 0.f;
    return g_wbe[b * NE + expert];
}

// ---------------- merged conversion + stageA kernel ----------------
// z == 0          : x fp32 -> fp16 into g_Xh
// z in 1..NE      : ew1 expert [D,H] -> [H,D]
// z == NE+1       : sw1 -> g_W1s
// z in NE+2..2NE+1: ew2 expert [H,D] -> [D,H]
// z == 2NE+2      : sw2 -> g_W2s
// z == 2NE+3      : gating stage A partial sums (blocks 0..47)
__global__ void k_conv(const float* __restrict__ x,
                       const float* __restrict__ ew1, const float* __restrict__ sw1,
                       const float* __restrict__ ew2, const float* __restrict__ sw2)
{
    int z = blockIdx.z;
    int ltid = threadIdx.y * 32 + threadIdx.x;   // 0..255
    if (z == 0) {
        int n4 = MT * DD / 4;
        int stride = gridDim.x * 256;
        for (int i = ltid + blockIdx.x * 256; i < n4; i += stride) {
            float4 v = reinterpret_cast<const float4*>(x)[i];
            __half2* d2 = reinterpret_cast<__half2*>(g_Xh) + (size_t)i * 2;
            d2[0] = __floats2half2_rn(v.x, v.y);
            d2[1] = __floats2half2_rn(v.z, v.w);
        }
        return;
    }
    if (z == 2 * NE + 3) {
        // gating stage A: blocks 0..47 -> (batch, chunk)
        if (blockIdx.x >= NB * 6) return;
        int b = blockIdx.x / 6, c = blockIdx.x % 6;
        const float* base = x + ((size_t)(b * LL + c * 128)) * DD;
        for (int d = ltid; d < DD; d += 256) {
            float s = 0.f;
            #pragma unroll 4
            for (int l = 0; l < 128; ++l) s += base[(size_t)l * DD + d];
            g_partial[(b * 6 + c) * DD + d] = s;
        }
        return;
    }
    const float* src;
    __half* dst;
    int R, C;
    if (z <= NE + 1) {                 // W1 family: [D,H] -> [H,D]
        R = DD; C = HH;
        if (z <= NE) { src = ew1 + (size_t)(z - 1) * R * C; dst = g_W1e + (size_t)(z - 1) * R * C; }
        else         { src = sw1; dst = g_W1s; }
    } else {                           // W2 family: [H,D] -> [D,H]
        R = HH; C = DD;
        int e = z - NE - 2;
        if (e < NE) { src = ew2 + (size_t)e * R * C; dst = g_W2e + (size_t)e * R * C; }
        else        { src = sw2; dst = g_W2s; }
    }
    // 64x64 transpose tiles: full 128B write lines
    int nCB = C / 64;
    int bx = blockIdx.x % nCB;
    int by = blockIdx.x / nCB;
    if (by >= R / 64) return;
    __shared__ float t[64][65];
    int c0 = bx * 64, r0 = by * 64;
    int tx = threadIdx.x, ty = threadIdx.y;
    #pragma unroll
    for (int j = 0; j < 8; j++) {
        int row = ty + j * 8;
        const float* sp = src + (size_t)(r0 + row) * C + c0;
        t[row][tx]      = sp[tx];
        t[row][tx + 32] = sp[tx + 32];
    }
    __syncthreads();
    #pragma unroll
    for (int j = 0; j < 8; j++) {
        int cc = ty + j * 8;                       // dst row = c0 + cc
        __half2 v = __floats2half2_rn(t[2 * tx][cc], t[2 * tx + 1][cc]);
        *reinterpret_cast<__half2*>(dst + (size_t)(c0 + cc) * R + r0 + 2 * tx) = v;
    }
}

// ---------------- gating stage B ----------------
__global__ void k_gate(const float* __restrict__ gate_w, const float* __restrict__ gate_b,
                       const float* __restrict__ time_cond, const float* __restrict__ time_w,
                       const float* __restrict__ time_b)
{
    int b = blockIdx.x, t = threadIdx.x;
    __shared__ float red[12][256];
    float acc[12];
    #pragma unroll
    for (int k = 0; k < 12; k++) acc[k] = 0.f;
    for (int d = t; d < DD; d += 256) {
        float h = g_partial[(b*6+0)*DD+d] + g_partial[(b*6+1)*DD+d];
        float w = g_partial[(b*6+2)*DD+d] + g_partial[(b*6+3)*DD+d];
        float p = g_partial[(b*6+4)*DD+d] + g_partial[(b*6+5)*DD+d];
        float full = (h + w + p) * (1.f / 768.f);
        float hp   = (h + p) * (1.f / 512.f);
        float wp   = (w + p) * (1.f / 512.f);
        #pragma unroll
        for (int e = 0; e < 4; e++)
            acc[e] += full * gate_w[d*4+e] + hp * gate_w[(DD+d)*4+e] + wp * gate_w[(2*DD+d)*4+e];
        float tc = time_cond[b * DD + d];
        float s  = tc / (1.f + expf(-tc));   // silu
        #pragma unroll
        for (int j = 0; j < 8; j++) acc[4 + j] += s * time_w[d*8 + j];
    }
    #pragma unroll
    for (int k = 0; k < 12; k++) red[k][t] = acc[k];
    __syncthreads();
    for (int s = 128; s > 0; s >>= 1) {
        if (t < s) {
            #pragma unroll
            for (int k = 0; k < 12; k++) red[k][t] += red[k][t + s];
        }
        __syncthreads();
    }
    if (t == 0) {
        float logit[4], prob[4];
        #pragma unroll
        for (int e = 0; e < 4; e++) {
            float sc = red[4 + e][0] + time_b[e];
            float sh = red[8 + e][0] + time_b[4 + e];
            logit[e] = (red[e][0] + gate_b[e]) * (1.f + sc) + sh;
        }
        float mx = fmaxf(fmaxf(logit[0], logit[1]), fmaxf(logit[2], logit[3]));
        float sum = 0.f;
        for (int e = 0; e < 4; e++) { prob[e] = expf(logit[e] - mx); sum += prob[e]; }
        for (int e = 0; e < 4; e++) prob[e] /= sum;
        int i1 = 0;
        for (int e = 1; e < 4; e++) if (prob[e] > prob[i1]) i1 = e;
        int i2 = -1;
        for (int e = 0; e < 4; e++) if (e != i1 && (i2 < 0 || prob[e] > prob[i2])) i2 = e;
        float denom = prob[i1] + prob[i2] + 1e-8f;
        #pragma unroll
        for (int e = 0; e < 4; e++) g_wbe[b * NE + e] = 0.f;
        g_wbe[b * NE + i1] = prob[i1] / denom;
        g_wbe[b * NE + i2] = prob[i2] / denom;
    }
}

// ---------------- GEMM1 (8 warps, warp tile 32x64): H[z] = w*gelu(X@W1[z] + b1[z]) ----------------
__global__ void __launch_bounds__(256, 2) k_mma1(
    const float* __restrict__ b_sh, const float* __restrict__ b_ex)
{
    constexpr int Ks = DD;
    constexpr int nch = Ks / KCH;

    int bm = blockIdx.x, bn = blockIdx.y, z = blockIdx.z;
    float w = tile_weight(z - 1, bm);
    if (w == 0.f) return;

    const __half* A = g_Xh;
    const __half* B = (z == 0) ? g_W1s : (g_W1e + (size_t)(z - 1) * HH * DD);
    const float* bias = (z == 0) ? b_sh : (b_ex + (size_t)(z - 1) * HH);
    __half* hout = g_H + (size_t)z * MT * HH;

    extern __shared__ __align__(128) char smem[];
    uint32_t sbase = smem_u32(smem);
    int tid = threadIdx.x, lane = tid & 31, wid = tid >> 5;
    int wm = wid & 3, wn = wid >> 2;
    int m0 = bm * 128, n0 = bn * 128;

    auto issue = [&](int it, int slot) {
        int koff = it * KCH;
        const __half* Ab = A + koff;
        const __half* Bb = B + koff;
        char* st = smem + slot * STG_BYTES;
        #pragma unroll
        for (int i = 0; i < 4; i++) {
            int idx = tid + i * 256;
            int r = idx >> 3, c8 = idx & 7;
            uint32_t off = (uint32_t)(r * 128 + c8 * 16);
            off ^= (off >> 3) & 0x70;
            cp_async16(st + off, Ab + (size_t)(m0 + r) * Ks + c8 * 8);
        }
        #pragma unroll
        for (int i = 0; i < 4; i++) {
            int idx = tid + i * 256;
            int r = idx >> 3, c8 = idx & 7;
            uint32_t off = (uint32_t)(r * 128 + c8 * 16);
            off ^= (off >> 3) & 0x70;
            cp_async16(st + TILE_BYTES + off, Bb + (size_t)(n0 + r) * Ks + c8 * 8);
        }
        cp_commit();
    };

    float c[2][8][4];
    #pragma unroll
    for (int i = 0; i < 2; i++)
        #pragma unroll
        for (int j = 0; j < 8; j++)
            #pragma unroll
            for (int q = 0; q < 4; q++) c[i][j][q] = 0.f;

    issue(0, 0);
    issue(1, 1);

    for (int it = 0; it < nch; ++it) {
        if (it + 1 < nch) asm volatile("cp.async.wait_group 1;" ::: "memory");
        else              asm volatile("cp.async.wait_group 0;" ::: "memory");
        __syncthreads();
        if (it + 2 < nch) issue(it + 2, (it + 2) % SS);

        uint32_t sAb = sbase + (it % SS) * STG_BYTES;
        uint32_t sBb = sAb + TILE_BYTES;
        #pragma unroll
        for (int kk = 0; kk < 4; kk++) {
            uint32_t a[2][4];
            #pragma unroll
            for (int i = 0; i < 2; i++) {
                int row = wm * 32 + i * 16 + (lane & 15);
                uint32_t off = (uint32_t)(row * 128 + kk * 32 + ((lane >> 4) & 1) * 16);
                off ^= (off >> 3) & 0x70;
                ldm4(a[i], sAb + off);
            }
            uint32_t b[8][2];
            #pragma unroll
            for (int jp = 0; jp < 4; jp++) {
                int n = wn * 64 + jp * 16 + ((lane >> 4) & 1) * 8 + (lane & 7);
                uint32_t off = (uint32_t)(n * 128 + kk * 32 + ((lane >> 3) & 1) * 16);
                off ^= (off >> 3) & 0x70;
                uint32_t r4[4];
                ldm4(r4, sBb + off);
                b[2 * jp][0] = r4[0]; b[2 * jp][1] = r4[1];
                b[2 * jp + 1][0] = r4[2]; b[2 * jp + 1][1] = r4[3];
            }
            #pragma unroll
            for (int i = 0; i < 2; i++)
                #pragma unroll
                for (int j = 0; j < 8; j++)
                    mma16816(c[i][j], a[i], b[j]);
        }
    }

    int gid = lane >> 2, tig = lane & 3;
    #pragma unroll
    for (int i = 0; i < 2; i++) {
        int r0i = m0 + wm * 32 + i * 16 + gid;
        #pragma unroll
        for (int j = 0; j < 8; j++) {
            int col = n0 + wn * 64 + j * 8 + tig * 2;
            float b0 = __ldg(bias + col);
            float b1 = __ldg(bias + col + 1);
            __half2 h0 = __floats2half2_rn(w * gelu_t(c[i][j][0] + b0),
                                           w * gelu_t(c[i][j][1] + b1));
            __half2 h1 = __floats2half2_rn(w * gelu_t(c[i][j][2] + b0),
                                           w * gelu_t(c[i][j][3] + b1));
            *reinterpret_cast<__half2*>(hout + (size_t)r0i * HH + col) = h0;
            *reinterpret_cast<__half2*>(hout + (size_t)(r0i + 8) * HH + col) = h1;
        }
    }
}

// ---------------- GEMM2: split-K(2) x segment-concat. P[zk] = sum over segs, K-half zk ----------------
__global__ void __launch_bounds__(256, 2) k_mma2()
{
    int bm = blockIdx.x, bn = blockIdx.y, zk = blockIdx.z;   // zk in {0,1}
    __shared__ const __half* sA[1 + NE];
    __shared__ const __half* sB[1 + NE];
    __shared__ int sNs;

    if (threadIdx.x == 0) {
        int ns = 0;
        sA[ns] = g_H; sB[ns] = g_W2s; ns++;
        for (int e = 0; e < NE; e++) {
            if (tile_weight(e, bm) > 0.f) {
                sA[ns] = g_H + (size_t)(e + 1) * MT * HH;
                sB[ns] = g_W2e + (size_t)e * DD * HH;
                ns++;
            }
        }
        sNs = ns;
    }
    __syncthreads();
    int ns = sNs;
    int nch = ns * 32;                  // 32 chunks = K-half (2048) per segment
    int kbase = zk * 2048;

    extern __shared__ __align__(128) char smem[];
    uint32_t sbase = smem_u32(smem);
    int tid = threadIdx.x, lane = tid & 31, wid = tid >> 5;
    int wm = wid & 3, wn = wid >> 2;
    int m0 = bm * 128, n0 = bn * 128;
    float* pout = g_P + (size_t)zk * MT * DD;

    auto issue = [&](int flat, int slot) {
        int seg = flat >> 5;
        int koff = kbase + (flat & 31) * KCH;
        const __half* Ab = sA[seg] + koff;
        const __half* Bb = sB[seg] + koff;
        char* st = smem + slot * STG_BYTES;
        #pragma unroll
        for (int i = 0; i < 4; i++) {
            int idx = tid + i * 256;
            int r = idx >> 3, c8 = idx & 7;
            uint32_t off = (uint32_t)(r * 128 + c8 * 16);
            off ^= (off >> 3) & 0x70;
            cp_async16(st + off, Ab + (size_t)(m0 + r) * HH + c8 * 8);
        }
        #pragma unroll
        for (int i = 0; i < 4; i++) {
            int idx = tid + i * 256;
            int r = idx >> 3, c8 = idx & 7;
            uint32_t off = (uint32_t)(r * 128 + c8 * 16);
            off ^= (off >> 3) & 0x70;
            cp_async16(st + TILE_BYTES + off, Bb + (size_t)(n0 + r) * HH + c8 * 8);
        }
        cp_commit();
    };

    float c[2][8][4];
    #pragma unroll
    for (int i = 0; i < 2; i++)
        #pragma unroll
        for (int j = 0; j < 8; j++)
            #pragma unroll
            for (int q = 0; q < 4; q++) c[i][j][q] = 0.f;

    issue(0, 0);
    issue(1, 1);

    for (int it = 0; it < nch; ++it) {
        if (it + 1 < nch) asm volatile("cp.async.wait_group 1;" ::: "memory");
        else              asm volatile("cp.async.wait_group 0;" ::: "memory");
        __syncthreads();
        if (it + 2 < nch) issue(it + 2, (it + 2) % SS);

        uint32_t sAb = sbase + (it % SS) * STG_BYTES;
        uint32_t sBb = sAb + TILE_BYTES;
        #pragma unroll
        for (int kk = 0; kk < 4; kk++) {
            uint32_t a[2][4];
            #pragma unroll
            for (int i = 0; i < 2; i++) {
                int row = wm * 32 + i * 16 + (lane & 15);
                uint32_t off = (uint32_t)(row * 128 + kk * 32 + ((lane >> 4) & 1) * 16);
                off ^= (off >> 3) & 0x70;
                ldm4(a[i], sAb + off);
            }
            uint32_t b[8][2];
            #pragma unroll
            for (int jp = 0; jp < 4; jp++) {
                int n = wn * 64 + jp * 16 + ((lane >> 4) & 1) * 8 + (lane & 7);
                uint32_t off = (uint32_t)(n * 128 + kk * 32 + ((lane >> 3) & 1) * 16);
                off ^= (off >> 3) & 0x70;
                uint32_t r4[4];
                ldm4(r4, sBb + off);
                b[2 * jp][0] = r4[0]; b[2 * jp][1] = r4[1];
                b[2 * jp + 1][0] = r4[2]; b[2 * jp + 1][1] = r4[3];
            }
            #pragma unroll
            for (int i = 0; i < 2; i++)
                #pragma unroll
                for (int j = 0; j < 8; j++)
                    mma16816(c[i][j], a[i], b[j]);
        }
    }

    int gid = lane >> 2, tig = lane & 3;
    #pragma unroll
    for (int i = 0; i < 2; i++) {
        int r0i = m0 + wm * 32 + i * 16 + gid;
        #pragma unroll
        for (int j = 0; j < 8; j++) {
            int col = n0 + wn * 64 + j * 8 + tig * 2;
            *reinterpret_cast<float2*>(pout + (size_t)r0i * DD + col) =
                make_float2(c[i][j][0], c[i][j][1]);
            *reinterpret_cast<float2*>(pout + (size_t)(r0i + 8) * DD + col) =
                make_float2(c[i][j][2], c[i][j][3]);
        }
    }
}

// ---------------- reduce: out = P0 + P1 + b_sh + sum_e w*mask*b2_e ----------------
__global__ void k_reduce(const float* __restrict__ b_sh, const float* __restrict__ b_ex,
                         float* __restrict__ out)
{
    int bm = blockIdx.x;                 // 128-row block
    int bn = blockIdx.y;                 // 128-col block
    float we[NE];
    #pragma unroll
    for (int e = 0; e < NE; e++) we[e] = tile_weight(e, bm);

    int tid = threadIdx.x;               // 256 threads
    size_t base = (size_t)bm * 128 * DD + bn * 128;
    for (int q = tid; q < 4096; q += 256) {
        int r = q >> 5;
        int c4 = (q & 31) << 2;
        size_t off = base + (size_t)r * DD + c4;
        int col = bn * 128 + c4;
        float4 acc = *reinterpret_cast<const float4*>(g_P + off);
        float4 p1  = *reinterpret_cast<const float4*>(g_P + (size_t)MT * DD + off);
        float4 bs  = *reinterpret_cast<const float4*>(b_sh + col);
        acc.x += p1.x + bs.x; acc.y += p1.y + bs.y;
        acc.z += p1.z + bs.z; acc.w += p1.w + bs.w;
        #pragma unroll
        for (int e = 0; e < NE; e++) {
            if (we[e] > 0.f) {
                float4 be = *reinterpret_cast<const float4*>(b_ex + (size_t)e * DD + col);
                acc.x += we[e] * be.x; acc.y += we[e] * be.y;
                acc.z += we[e] * be.z; acc.w += we[e] * be.w;
            }
        }
        *reinterpret_cast<float4*>(out + off) = acc;
    }
}

// ---------------- launch ----------------
extern "C" void kernel_launch(void* const* d_in, const int* in_sizes, int n_in,
                              void* d_out, int out_size)
{
    (void)in_sizes; (void)n_in; (void)out_size;
    const float* x         = (const float*)d_in[0];
    const float* time_cond = (const float*)d_in[1];
    const float* gate_w    = (const float*)d_in[2];
    const float* gate_b    = (const float*)d_in[3];
    const float* time_w    = (const float*)d_in[4];
    const float* time_b    = (const float*)d_in[5];
    const float* ew1       = (const float*)d_in[6];
    const float* eb1       = (const float*)d_in[7];
    const float* ew2       = (const float*)d_in[8];
    const float* eb2       = (const float*)d_in[9];
    const float* sw1       = (const float*)d_in[10];
    const float* sb1       = (const float*)d_in[11];
    const float* sw2       = (const float*)d_in[12];
    const float* sb2       = (const float*)d_in[13];
    float* out = (float*)d_out;

    cudaFuncSetAttribute(k_mma1, cudaFuncAttributeMaxDynamicSharedMemorySize, GEMM_SMEM);
    cudaFuncSetAttribute(k_mma2, cudaFuncAttributeMaxDynamicSharedMemorySize, GEMM_SMEM);

    // 1) conversions + gating stage A, one launch (z = 12 slices; 64x64 transpose tiles)
    k_conv<<<dim3(1024, 1, 2 * NE + 4), dim3(32, 8)>>>(x, ew1, sw1, ew2, sw2);
    // 2) gating stage B
    k_gate<<<8, 256>>>(gate_w, gate_b, time_cond, time_w, time_b);
    // 3) GEMM1: shared + 4 experts; inactive tiles exit
    k_mma1<<<dim3(MT / 128, HH / 128, 5), 256, GEMM_SMEM>>>(sb1, eb1);
    // 4) GEMM2: split-K(2) with in-CTA segment concat -> 2 fp32 partials
    k_mma2<<<dim3(MT / 128, DD / 128, 2), 256, GEMM_SMEM>>>();
    // 5) combine partials + biases into out (single deterministic write)
    k_reduce<<<dim3(MT / 128, DD / 128), 256>>>(sb2, eb2, out);
}

// round 11
// speedup vs baseline: 1.3432x; 1.0152x over previous
#include <cuda_runtime.h>
#include <cuda_fp16.h>
#include <cstdint>

#define DD 1024
#define HH 4096
#define NB 8
#define LL 768
#define MT 6144   // NB*LL
#define NE 4

#define KCH 64               // K halfs per chunk (128B rows)
#define SS 3                 // pipeline stages
#define TILE_BYTES 16384     // 128 rows x 128B
#define STG_BYTES 32768      // A tile + B tile
#define GEMM_SMEM (SS * STG_BYTES)   // 96 KB -> 2 CTAs/SM

// ---------------- scratch (device globals; no allocation) ----------------
__device__ __align__(256) __half g_Xh[(size_t)MT * DD];
__device__ __align__(256) __half g_W1e[(size_t)NE * HH * DD];  // W1^T per expert: [H][D]
__device__ __align__(256) __half g_W2e[(size_t)NE * DD * HH];  // W2^T per expert: [D][H]
__device__ __align__(256) __half g_W1s[(size_t)HH * DD];       // sw1^T
__device__ __align__(256) __half g_W2s[(size_t)DD * HH];       // sw2^T
__device__ __align__(256) __half g_H[(size_t)5 * MT * HH];     // [shared, e0..e3] hidden
__device__ __align__(256) float  g_P[(size_t)2 * MT * DD];     // GEMM2 split-K partials
__device__ float  g_partial[NB * 6 * DD];
__device__ float  g_wbe[NB * NE];

// ---------------- helpers ----------------
__device__ __forceinline__ uint32_t smem_u32(const void* p) {
    uint32_t a;
    asm("{ .reg .u64 t; cvta.to.shared.u64 t, %1; cvt.u32.u64 %0, t; }" : "=r"(a) : "l"(p));
    return a;
}
__device__ __forceinline__ void cp_async16(void* smem, const void* gmem) {
    unsigned s = (unsigned)__cvta_generic_to_shared(smem);
    asm volatile("cp.async.cg.shared.global [%0], [%1], 16;\n" :: "r"(s), "l"(gmem) : "memory");
}
__device__ __forceinline__ void cp_commit() { asm volatile("cp.async.commit_group;\n" ::: "memory"); }

__device__ __forceinline__ void ldm4(uint32_t* r, uint32_t addr) {
    asm volatile("ldmatrix.sync.aligned.m8n8.x4.shared.b16 {%0,%1,%2,%3}, [%4];"
        : "=r"(r[0]), "=r"(r[1]), "=r"(r[2]), "=r"(r[3]) : "r"(addr));
}
__device__ __forceinline__ void mma16816(float* c, const uint32_t* a, const uint32_t* b) {
    asm volatile(
        "mma.sync.aligned.m16n8k16.row.col.f32.f16.f16.f32 "
        "{%0,%1,%2,%3}, {%4,%5,%6,%7}, {%8,%9}, {%0,%1,%2,%3};"
        : "+f"(c[0]), "+f"(c[1]), "+f"(c[2]), "+f"(c[3])
        : "r"(a[0]), "r"(a[1]), "r"(a[2]), "r"(a[3]), "r"(b[0]), "r"(b[1]));
}

// fast GELU (tanh approx via single-instruction MUFU tanh)
__device__ __forceinline__ float gelu_t(float v) {
    float c = 0.7978845608028654f * (v + 0.044715f * v * v * v);
    float t;
    asm("tanh.approx.f32 %0, %1;" : "=f"(t) : "f"(c));
    return 0.5f * v * (1.f + t);
}

// per-M-tile weight: batch gating weight x third-mask; exact 0 => skip tile
__device__ __forceinline__ float tile_weight(int expert, int bm) {
    if (expert < 0) return 1.f;
    int b = bm / 6;             // 6 tiles of 128 tokens per batch
    int third = (bm % 6) >> 1;  // 0 head, 1 wrist, 2 proprio
    if (expert == 1 && third == 1) return 0.f;
    if (expert == 2 && third == 0) return 0.f;
    return g_wbe[b * NE + expert];
}

// ---------------- merged conversion + stageA kernel ----------------
__global__ void k_conv(const float* __restrict__ x,
                       const float* __restrict__ ew1, const float* __restrict__ sw1,
                       const float* __restrict__ ew2, const float* __restrict__ sw2)
{
    int z = blockIdx.z;
    int ltid = threadIdx.y * 32 + threadIdx.x;   // 0..255
    if (z == 0) {
        int n4 = MT * DD / 4;
        int stride = gridDim.x * 256;
        for (int i = ltid + blockIdx.x * 256; i < n4; i += stride) {
            float4 v = reinterpret_cast<const float4*>(x)[i];
            __half2* d2 = reinterpret_cast<__half2*>(g_Xh) + (size_t)i * 2;
            d2[0] = __floats2half2_rn(v.x, v.y);
            d2[1] = __floats2half2_rn(v.z, v.w);
        }
        return;
    }
    if (z == 2 * NE + 3) {
        if (blockIdx.x >= NB * 6) return;
        int b = blockIdx.x / 6, c = blockIdx.x % 6;
        const float* base = x + ((size_t)(b * LL + c * 128)) * DD;
        for (int d = ltid; d < DD; d += 256) {
            float s = 0.f;
            #pragma unroll 4
            for (int l = 0; l < 128; ++l) s += base[(size_t)l * DD + d];
            g_partial[(b * 6 + c) * DD + d] = s;
        }
        return;
    }
    const float* src;
    __half* dst;
    int R, C;
    if (z <= NE + 1) {                 // W1 family: [D,H] -> [H,D]
        R = DD; C = HH;
        if (z <= NE) { src = ew1 + (size_t)(z - 1) * R * C; dst = g_W1e + (size_t)(z - 1) * R * C; }
        else         { src = sw1; dst = g_W1s; }
    } else {                           // W2 family: [H,D] -> [D,H]
        R = HH; C = DD;
        int e = z - NE - 2;
        if (e < NE) { src = ew2 + (size_t)e * R * C; dst = g_W2e + (size_t)e * R * C; }
        else        { src = sw2; dst = g_W2s; }
    }
    int nCB = C / 64;
    int bx = blockIdx.x % nCB;
    int by = blockIdx.x / nCB;
    if (by >= R / 64) return;
    __shared__ float t[64][65];
    int c0 = bx * 64, r0 = by * 64;
    int tx = threadIdx.x, ty = threadIdx.y;
    #pragma unroll
    for (int j = 0; j < 8; j++) {
        int row = ty + j * 8;
        const float* sp = src + (size_t)(r0 + row) * C + c0;
        t[row][tx]      = sp[tx];
        t[row][tx + 32] = sp[tx + 32];
    }
    __syncthreads();
    #pragma unroll
    for (int j = 0; j < 8; j++) {
        int cc = ty + j * 8;
        __half2 v = __floats2half2_rn(t[2 * tx][cc], t[2 * tx + 1][cc]);
        *reinterpret_cast<__half2*>(dst + (size_t)(c0 + cc) * R + r0 + 2 * tx) = v;
    }
}

// ---------------- gating stage B ----------------
__global__ void k_gate(const float* __restrict__ gate_w, const float* __restrict__ gate_b,
                       const float* __restrict__ time_cond, const float* __restrict__ time_w,
                       const float* __restrict__ time_b)
{
    int b = blockIdx.x, t = threadIdx.x;
    __shared__ float red[12][256];
    float acc[12];
    #pragma unroll
    for (int k = 0; k < 12; k++) acc[k] = 0.f;
    for (int d = t; d < DD; d += 256) {
        float h = g_partial[(b*6+0)*DD+d] + g_partial[(b*6+1)*DD+d];
        float w = g_partial[(b*6+2)*DD+d] + g_partial[(b*6+3)*DD+d];
        float p = g_partial[(b*6+4)*DD+d] + g_partial[(b*6+5)*DD+d];
        float full = (h + w + p) * (1.f / 768.f);
        float hp   = (h + p) * (1.f / 512.f);
        float wp   = (w + p) * (1.f / 512.f);
        #pragma unroll
        for (int e = 0; e < 4; e++)
            acc[e] += full * gate_w[d*4+e] + hp * gate_w[(DD+d)*4+e] + wp * gate_w[(2*DD+d)*4+e];
        float tc = time_cond[b * DD + d];
        float s  = tc / (1.f + expf(-tc));   // silu
        #pragma unroll
        for (int j = 0; j < 8; j++) acc[4 + j] += s * time_w[d*8 + j];
    }
    #pragma unroll
    for (int k = 0; k < 12; k++) red[k][t] = acc[k];
    __syncthreads();
    for (int s = 128; s > 0; s >>= 1) {
        if (t < s) {
            #pragma unroll
            for (int k = 0; k < 12; k++) red[k][t] += red[k][t + s];
        }
        __syncthreads();
    }
    if (t == 0) {
        float logit[4], prob[4];
        #pragma unroll
        for (int e = 0; e < 4; e++) {
            float sc = red[4 + e][0] + time_b[e];
            float sh = red[8 + e][0] + time_b[4 + e];
            logit[e] = (red[e][0] + gate_b[e]) * (1.f + sc) + sh;
        }
        float mx = fmaxf(fmaxf(logit[0], logit[1]), fmaxf(logit[2], logit[3]));
        float sum = 0.f;
        for (int e = 0; e < 4; e++) { prob[e] = expf(logit[e] - mx); sum += prob[e]; }
        for (int e = 0; e < 4; e++) prob[e] /= sum;
        int i1 = 0;
        for (int e = 1; e < 4; e++) if (prob[e] > prob[i1]) i1 = e;
        int i2 = -1;
        for (int e = 0; e < 4; e++) if (e != i1 && (i2 < 0 || prob[e] > prob[i2])) i2 = e;
        float denom = prob[i1] + prob[i2] + 1e-8f;
        #pragma unroll
        for (int e = 0; e < 4; e++) g_wbe[b * NE + e] = 0.f;
        g_wbe[b * NE + i1] = prob[i1] / denom;
        g_wbe[b * NE + i2] = prob[i2] / denom;
    }
}

// ---------------- GEMM1: 2 N-tiles per CTA, continuous 32-chunk pipeline ----------------
// H[z] = w * gelu(X @ W1[z] + b1[z]);  z = 0 shared, 1..4 experts
__global__ void __launch_bounds__(256, 2) k_mma1(
    const float* __restrict__ b_sh, const float* __restrict__ b_ex)
{
    constexpr int NCHT = DD / KCH;      // 16 chunks per tile
    constexpr int NT = 2;               // tiles per CTA
    constexpr int nch = NCHT * NT;      // 32 chunks total

    int bm = blockIdx.x, bn0 = blockIdx.y * NT, z = blockIdx.z;
    float w = tile_weight(z - 1, bm);
    if (w == 0.f) return;

    const __half* A = g_Xh;
    const __half* B = (z == 0) ? g_W1s : (g_W1e + (size_t)(z - 1) * HH * DD);
    const float* bias = (z == 0) ? b_sh : (b_ex + (size_t)(z - 1) * HH);
    __half* hout = g_H + (size_t)z * MT * HH;

    extern __shared__ __align__(128) char smem[];
    uint32_t sbase = smem_u32(smem);
    int tid = threadIdx.x, lane = tid & 31, wid = tid >> 5;
    int wm = wid & 3, wn = wid >> 2;
    int m0 = bm * 128;

    auto issue = [&](int flat, int slot) {
        int tile  = flat >> 4;          // 0..1
        int chunk = flat & (NCHT - 1);
        int koff = chunk * KCH;
        int n0 = (bn0 + tile) * 128;
        const __half* Ab = A + koff;
        const __half* Bb = B + koff;
        char* st = smem + slot * STG_BYTES;
        #pragma unroll
        for (int i = 0; i < 4; i++) {
            int idx = tid + i * 256;
            int r = idx >> 3, c8 = idx & 7;
            uint32_t off = (uint32_t)(r * 128 + c8 * 16);
            off ^= (off >> 3) & 0x70;
            cp_async16(st + off, Ab + (size_t)(m0 + r) * DD + c8 * 8);
        }
        #pragma unroll
        for (int i = 0; i < 4; i++) {
            int idx = tid + i * 256;
            int r = idx >> 3, c8 = idx & 7;
            uint32_t off = (uint32_t)(r * 128 + c8 * 16);
            off ^= (off >> 3) & 0x70;
            cp_async16(st + TILE_BYTES + off, Bb + (size_t)(n0 + r) * DD + c8 * 8);
        }
        cp_commit();
    };

    float c[2][8][4];
    #pragma unroll
    for (int i = 0; i < 2; i++)
        #pragma unroll
        for (int j = 0; j < 8; j++)
            #pragma unroll
            for (int q = 0; q < 4; q++) c[i][j][q] = 0.f;

    int gid = lane >> 2, tig = lane & 3;
    auto epilogue = [&](int tile) {
        int n0 = (bn0 + tile) * 128;
        #pragma unroll
        for (int i = 0; i < 2; i++) {
            int r0i = m0 + wm * 32 + i * 16 + gid;
            #pragma unroll
            for (int j = 0; j < 8; j++) {
                int col = n0 + wn * 64 + j * 8 + tig * 2;
                float b0 = __ldg(bias + col);
                float b1 = __ldg(bias + col + 1);
                __half2 h0 = __floats2half2_rn(w * gelu_t(c[i][j][0] + b0),
                                               w * gelu_t(c[i][j][1] + b1));
                __half2 h1 = __floats2half2_rn(w * gelu_t(c[i][j][2] + b0),
                                               w * gelu_t(c[i][j][3] + b1));
                *reinterpret_cast<__half2*>(hout + (size_t)r0i * HH + col) = h0;
                *reinterpret_cast<__half2*>(hout + (size_t)(r0i + 8) * HH + col) = h1;
                c[i][j][0] = c[i][j][1] = c[i][j][2] = c[i][j][3] = 0.f;   // reset for next tile
            }
        }
    };

    issue(0, 0);
    issue(1, 1);

    for (int it = 0; it < nch; ++it) {
        if (it + 1 < nch) asm volatile("cp.async.wait_group 1;" ::: "memory");
        else              asm volatile("cp.async.wait_group 0;" ::: "memory");
        __syncthreads();
        if (it + 2 < nch) issue(it + 2, (it + 2) % SS);

        uint32_t sAb = sbase + (it % SS) * STG_BYTES;
        uint32_t sBb = sAb + TILE_BYTES;
        #pragma unroll
        for (int kk = 0; kk < 4; kk++) {
            uint32_t a[2][4];
            #pragma unroll
            for (int i = 0; i < 2; i++) {
                int row = wm * 32 + i * 16 + (lane & 15);
                uint32_t off = (uint32_t)(row * 128 + kk * 32 + ((lane >> 4) & 1) * 16);
                off ^= (off >> 3) & 0x70;
                ldm4(a[i], sAb + off);
            }
            uint32_t b[8][2];
            #pragma unroll
            for (int jp = 0; jp < 4; jp++) {
                int n = wn * 64 + jp * 16 + ((lane >> 4) & 1) * 8 + (lane & 7);
                uint32_t off = (uint32_t)(n * 128 + kk * 32 + ((lane >> 3) & 1) * 16);
                off ^= (off >> 3) & 0x70;
                uint32_t r4[4];
                ldm4(r4, sBb + off);
                b[2 * jp][0] = r4[0]; b[2 * jp][1] = r4[1];
                b[2 * jp + 1][0] = r4[2]; b[2 * jp + 1][1] = r4[3];
            }
            #pragma unroll
            for (int i = 0; i < 2; i++)
                #pragma unroll
                for (int j = 0; j < 8; j++)
                    mma16816(c[i][j], a[i], b[j]);
        }
        if ((it & (NCHT - 1)) == NCHT - 1)
            epilogue(it >> 4);          // mid-stream epilogue; loads for next tile already in flight
    }
}

// ---------------- GEMM2: split-K(2) x segment-concat. P[zk] = sum over segs, K-half zk ----------------
__global__ void __launch_bounds__(256, 2) k_mma2()
{
    int bm = blockIdx.x, bn = blockIdx.y, zk = blockIdx.z;   // zk in {0,1}
    __shared__ const __half* sA[1 + NE];
    __shared__ const __half* sB[1 + NE];
    __shared__ int sNs;

    if (threadIdx.x == 0) {
        int ns = 0;
        sA[ns] = g_H; sB[ns] = g_W2s; ns++;
        for (int e = 0; e < NE; e++) {
            if (tile_weight(e, bm) > 0.f) {
                sA[ns] = g_H + (size_t)(e + 1) * MT * HH;
                sB[ns] = g_W2e + (size_t)e * DD * HH;
                ns++;
            }
        }
        sNs = ns;
    }
    __syncthreads();
    int ns = sNs;
    int nch = ns * 32;                  // 32 chunks = K-half (2048) per segment
    int kbase = zk * 2048;

    extern __shared__ __align__(128) char smem[];
    uint32_t sbase = smem_u32(smem);
    int tid = threadIdx.x, lane = tid & 31, wid = tid >> 5;
    int wm = wid & 3, wn = wid >> 2;
    int m0 = bm * 128, n0 = bn * 128;
    float* pout = g_P + (size_t)zk * MT * DD;

    auto issue = [&](int flat, int slot) {
        int seg = flat >> 5;
        int koff = kbase + (flat & 31) * KCH;
        const __half* Ab = sA[seg] + koff;
        const __half* Bb = sB[seg] + koff;
        char* st = smem + slot * STG_BYTES;
        #pragma unroll
        for (int i = 0; i < 4; i++) {
            int idx = tid + i * 256;
            int r = idx >> 3, c8 = idx & 7;
            uint32_t off = (uint32_t)(r * 128 + c8 * 16);
            off ^= (off >> 3) & 0x70;
            cp_async16(st + off, Ab + (size_t)(m0 + r) * HH + c8 * 8);
        }
        #pragma unroll
        for (int i = 0; i < 4; i++) {
            int idx = tid + i * 256;
            int r = idx >> 3, c8 = idx & 7;
            uint32_t off = (uint32_t)(r * 128 + c8 * 16);
            off ^= (off >> 3) & 0x70;
            cp_async16(st + TILE_BYTES + off, Bb + (size_t)(n0 + r) * HH + c8 * 8);
        }
        cp_commit();
    };

    float c[2][8][4];
    #pragma unroll
    for (int i = 0; i < 2; i++)
        #pragma unroll
        for (int j = 0; j < 8; j++)
            #pragma unroll
            for (int q = 0; q < 4; q++) c[i][j][q] = 0.f;

    issue(0, 0);
    issue(1, 1);

    for (int it = 0; it < nch; ++it) {
        if (it + 1 < nch) asm volatile("cp.async.wait_group 1;" ::: "memory");
        else              asm volatile("cp.async.wait_group 0;" ::: "memory");
        __syncthreads();
        if (it + 2 < nch) issue(it + 2, (it + 2) % SS);

        uint32_t sAb = sbase + (it % SS) * STG_BYTES;
        uint32_t sBb = sAb + TILE_BYTES;
        #pragma unroll
        for (int kk = 0; kk < 4; kk++) {
            uint32_t a[2][4];
            #pragma unroll
            for (int i = 0; i < 2; i++) {
                int row = wm * 32 + i * 16 + (lane & 15);
                uint32_t off = (uint32_t)(row * 128 + kk * 32 + ((lane >> 4) & 1) * 16);
                off ^= (off >> 3) & 0x70;
                ldm4(a[i], sAb + off);
            }
            uint32_t b[8][2];
            #pragma unroll
            for (int jp = 0; jp < 4; jp++) {
                int n = wn * 64 + jp * 16 + ((lane >> 4) & 1) * 8 + (lane & 7);
                uint32_t off = (uint32_t)(n * 128 + kk * 32 + ((lane >> 3) & 1) * 16);
                off ^= (off >> 3) & 0x70;
                uint32_t r4[4];
                ldm4(r4, sBb + off);
                b[2 * jp][0] = r4[0]; b[2 * jp][1] = r4[1];
                b[2 * jp + 1][0] = r4[2]; b[2 * jp + 1][1] = r4[3];
            }
            #pragma unroll
            for (int i = 0; i < 2; i++)
                #pragma unroll
                for (int j = 0; j < 8; j++)
                    mma16816(c[i][j], a[i], b[j]);
        }
    }

    int gid = lane >> 2, tig = lane & 3;
    #pragma unroll
    for (int i = 0; i < 2; i++) {
        int r0i = m0 + wm * 32 + i * 16 + gid;
        #pragma unroll
        for (int j = 0; j < 8; j++) {
            int col = n0 + wn * 64 + j * 8 + tig * 2;
            *reinterpret_cast<float2*>(pout + (size_t)r0i * DD + col) =
                make_float2(c[i][j][0], c[i][j][1]);
            *reinterpret_cast<float2*>(pout + (size_t)(r0i + 8) * DD + col) =
                make_float2(c[i][j][2], c[i][j][3]);
        }
    }
}

// ---------------- reduce: out = P0 + P1 + b_sh + sum_e w*mask*b2_e ----------------
__global__ void k_reduce(const float* __restrict__ b_sh, const float* __restrict__ b_ex,
                         float* __restrict__ out)
{
    int bm = blockIdx.x;
    int bn = blockIdx.y;
    float we[NE];
    #pragma unroll
    for (int e = 0; e < NE; e++) we[e] = tile_weight(e, bm);

    int tid = threadIdx.x;
    size_t base = (size_t)bm * 128 * DD + bn * 128;
    for (int q = tid; q < 4096; q += 256) {
        int r = q >> 5;
        int c4 = (q & 31) << 2;
        size_t off = base + (size_t)r * DD + c4;
        int col = bn * 128 + c4;
        float4 acc = *reinterpret_cast<const float4*>(g_P + off);
        float4 p1  = *reinterpret_cast<const float4*>(g_P + (size_t)MT * DD + off);
        float4 bs  = *reinterpret_cast<const float4*>(b_sh + col);
        acc.x += p1.x + bs.x; acc.y += p1.y + bs.y;
        acc.z += p1.z + bs.z; acc.w += p1.w + bs.w;
        #pragma unroll
        for (int e = 0; e < NE; e++) {
            if (we[e] > 0.f) {
                float4 be = *reinterpret_cast<const float4*>(b_ex + (size_t)e * DD + col);
                acc.x += we[e] * be.x; acc.y += we[e] * be.y;
                acc.z += we[e] * be.z; acc.w += we[e] * be.w;
            }
        }
        *reinterpret_cast<float4*>(out + off) = acc;
    }
}

// ---------------- launch ----------------
extern "C" void kernel_launch(void* const* d_in, const int* in_sizes, int n_in,
                              void* d_out, int out_size)
{
    (void)in_sizes; (void)n_in; (void)out_size;
    const float* x         = (const float*)d_in[0];
    const float* time_cond = (const float*)d_in[1];
    const float* gate_w    = (const float*)d_in[2];
    const float* gate_b    = (const float*)d_in[3];
    const float* time_w    = (const float*)d_in[4];
    const float* time_b    = (const float*)d_in[5];
    const float* ew1       = (const float*)d_in[6];
    const float* eb1       = (const float*)d_in[7];
    const float* ew2       = (const float*)d_in[8];
    const float* eb2       = (const float*)d_in[9];
    const float* sw1       = (const float*)d_in[10];
    const float* sb1       = (const float*)d_in[11];
    const float* sw2       = (const float*)d_in[12];
    const float* sb2       = (const float*)d_in[13];
    float* out = (float*)d_out;

    cudaFuncSetAttribute(k_mma1, cudaFuncAttributeMaxDynamicSharedMemorySize, GEMM_SMEM);
    cudaFuncSetAttribute(k_mma2, cudaFuncAttributeMaxDynamicSharedMemorySize, GEMM_SMEM);

    // 1) conversions + gating stage A, one launch
    k_conv<<<dim3(1024, 1, 2 * NE + 4), dim3(32, 8)>>>(x, ew1, sw1, ew2, sw2);
    // 2) gating stage B
    k_gate<<<8, 256>>>(gate_w, gate_b, time_cond, time_w, time_b);
    // 3) GEMM1: 2 N-tiles per CTA; shared + 4 experts; inactive tiles exit
    k_mma1<<<dim3(MT / 128, HH / 256, 5), 256, GEMM_SMEM>>>(sb1, eb1);
    // 4) GEMM2: split-K(2) with in-CTA segment concat -> 2 fp32 partials
    k_mma2<<<dim3(MT / 128, DD / 128, 2), 256, GEMM_SMEM>>>();
    // 5) combine partials + biases into out (single deterministic write)
    k_reduce<<<dim3(MT / 128, DD / 128), 256>>>(sb2, eb2, out);
}